// round 4
// baseline (speedup 1.0000x reference)
#include <cuda_runtime.h>
#include <cuda_bf16.h>

// Problem constants (match reference)
#define NN 50000
#define EE 600000
#define GG 64
#define HH 128
#define CC 10

// ---------------- scratch (static device globals; no runtime alloc) ----------------
__device__ int   g_is64;           // 1 if index tensors are int64, 0 if int32
__device__ int   g_deg[NN];        // in-degree (without self loop)
__device__ int   g_off[NN];        // CSR exclusive offsets
__device__ int   g_fill[NN];       // CSR fill cursors
__device__ float g_dinv[NN];       // rsqrt(deg+1)
__device__ int2  g_csr[EE];        // {src, bits(dinv[src])} grouped by dst
__device__ float g_bufA[NN * HH];  // xa  (then reused for Agg(h))
__device__ float g_bufB[NN * HH];  // h = relu(xa@W1+b1)
__device__ float g_sums[GG * HH];  // per-graph feature sums
__device__ float g_cnt[GG];        // per-graph node counts
__device__ float g_Wc[HH * CC];    // W2 @ Wlin
__device__ float g_bc[CC];         // b2 @ Wlin + blin

// ---------------- index load helper (dtype-agnostic) ----------------
__device__ __forceinline__ int load_idx(const void* p, long long i, int is64) {
    if (is64) return (int)(((const long long*)p)[i]);
    return ((const int*)p)[i];
}

// ---------------- K_detect: decide int32 vs int64 for index tensors ------------
// If the buffer truly holds int64 node indices, every 64-bit word is in [0, NN).
// If it holds int32, a 64-bit read fuses two values: lo + hi*2^32, which is huge
// whenever the odd-position value is nonzero (prob ~1 - 1/NN per word).
__global__ void detect_kernel(const void* ei) {
    __shared__ int bad;
    if (threadIdx.x == 0) bad = 0;
    __syncthreads();
    const long long* p = (const long long*)ei;
    for (int i = threadIdx.x; i < 4096; i += blockDim.x) {
        long long v = p[i];   // safe: buffer is >= 4.8MB in either dtype
        if (v < 0 || v >= (long long)NN) bad = 1;
    }
    __syncthreads();
    if (threadIdx.x == 0) g_is64 = bad ? 0 : 1;
}

// ---------------- K0: zero scratch used with atomics ----------------
__global__ void zero_kernel() {
    int i = blockIdx.x * blockDim.x + threadIdx.x;
    if (i < NN) { g_deg[i] = 0; g_fill[i] = 0; }
    if (i < GG * HH) g_sums[i] = 0.f;
    if (i < GG) g_cnt[i] = 0.f;
}

// ---------------- K1: count in-degrees ----------------
__global__ void deg_kernel(const void* __restrict__ ei) {
    int e = blockIdx.x * blockDim.x + threadIdx.x;
    if (e < EE) {
        int is64 = g_is64;
        int dst = load_idx(ei, (long long)EE + e, is64);
        dst = min(max(dst, 0), NN - 1);      // clamp: never crash
        atomicAdd(&g_deg[dst], 1);
    }
}

// ---------------- K2: single-block exclusive scan + dinv ----------------
__global__ void scan_kernel() {
    __shared__ int sh[1024];
    __shared__ int carry;
    int tid = threadIdx.x;
    if (tid == 0) carry = 0;
    __syncthreads();
    for (int base = 0; base < NN; base += 1024) {
        int i = base + tid;
        int v = (i < NN) ? g_deg[i] : 0;
        if (i < NN) g_dinv[i] = rsqrtf((float)(v + 1));
        sh[tid] = v;
        __syncthreads();
        #pragma unroll
        for (int s = 1; s < 1024; s <<= 1) {
            int t = (tid >= s) ? sh[tid - s] : 0;
            __syncthreads();
            if (tid >= s) sh[tid] += t;
            __syncthreads();
        }
        if (i < NN) g_off[i] = carry + sh[tid] - v;   // exclusive
        __syncthreads();
        if (tid == 0) carry += sh[1023];
        __syncthreads();
    }
}

// ---------------- K3: scatter edges into dst-grouped CSR ----------------
__global__ void fill_kernel(const void* __restrict__ ei) {
    int e = blockIdx.x * blockDim.x + threadIdx.x;
    if (e < EE) {
        int is64 = g_is64;
        int src = load_idx(ei, e, is64);
        int dst = load_idx(ei, (long long)EE + e, is64);
        src = min(max(src, 0), NN - 1);
        dst = min(max(dst, 0), NN - 1);
        int pos = g_off[dst] + atomicAdd(&g_fill[dst], 1);
        g_csr[pos] = make_int2(src, __float_as_int(g_dinv[src]));
    }
}

// ---------------- K4/K6: aggregation (warp per dst node, float4 per lane) ----------
__device__ __forceinline__ void fma4(float4& a, float w, const float4& v) {
    a.x = fmaf(w, v.x, a.x); a.y = fmaf(w, v.y, a.y);
    a.z = fmaf(w, v.z, a.z); a.w = fmaf(w, v.w, a.w);
}

__global__ void __launch_bounds__(256) agg_kernel(const float* __restrict__ in,
                                                  float* __restrict__ out) {
    int warp = (blockIdx.x * blockDim.x + threadIdx.x) >> 5;
    int lane = threadIdx.x & 31;
    if (warp >= NN) return;
    int dst = warp;
    float di = g_dinv[dst];
    const float4* sf = (const float4*)in;

    // self-loop term: dinv[dst] * x[dst] inside the sum
    float4 a0 = sf[dst * 32 + lane];
    a0.x *= di; a0.y *= di; a0.z *= di; a0.w *= di;
    float4 a1 = make_float4(0.f, 0.f, 0.f, 0.f);
    float4 a2 = make_float4(0.f, 0.f, 0.f, 0.f);
    float4 a3 = make_float4(0.f, 0.f, 0.f, 0.f);

    int e = g_off[dst];
    int end = e + g_deg[dst];
    // 4-way unroll: 4 independent row loads in flight
    for (; e + 3 < end; e += 4) {
        int2 e0 = g_csr[e + 0];
        int2 e1 = g_csr[e + 1];
        int2 e2 = g_csr[e + 2];
        int2 e3 = g_csr[e + 3];
        float4 v0 = sf[e0.x * 32 + lane];
        float4 v1 = sf[e1.x * 32 + lane];
        float4 v2 = sf[e2.x * 32 + lane];
        float4 v3 = sf[e3.x * 32 + lane];
        fma4(a0, __int_as_float(e0.y), v0);
        fma4(a1, __int_as_float(e1.y), v1);
        fma4(a2, __int_as_float(e2.y), v2);
        fma4(a3, __int_as_float(e3.y), v3);
    }
    for (; e < end; e++) {
        int2 en = g_csr[e];
        float4 v = sf[en.x * 32 + lane];
        fma4(a0, __int_as_float(en.y), v);
    }
    a0.x += a1.x + a2.x + a3.x;
    a0.y += a1.y + a2.y + a3.y;
    a0.z += a1.z + a2.z + a3.z;
    a0.w += a1.w + a2.w + a3.w;
    a0.x *= di; a0.y *= di; a0.z *= di; a0.w *= di;
    ((float4*)out)[dst * 32 + lane] = a0;
}

// ---------------- K5: fused SGEMM  h = relu(xa @ W1 + b1) ----------------
// M=NN, N=128, K=128.  Block 128x128, BK=16, 256 threads, 8x8 per thread.
__global__ void __launch_bounds__(256) gemm_bias_relu(const float* __restrict__ A,
                                                      const float* __restrict__ B,
                                                      const float* __restrict__ bias,
                                                      float* __restrict__ Cout) {
    const int BK = 16;
    __shared__ float As[BK][128];
    __shared__ float Bs[BK][128];
    int tid = threadIdx.x;
    int row0 = blockIdx.x * 128;
    int tx = tid & 15;   // col group (8 cols)
    int ty = tid >> 4;   // row group (8 rows)
    float acc[8][8];
    #pragma unroll
    for (int i = 0; i < 8; i++)
        #pragma unroll
        for (int j = 0; j < 8; j++) acc[i][j] = 0.f;

    for (int k0 = 0; k0 < 128; k0 += BK) {
        // load A tile (128 rows x 16 k), transposed into As[k][m]
        #pragma unroll
        for (int l = 0; l < 2; l++) {
            int idx = tid + l * 256;      // float4 slot 0..511
            int m = idx >> 2;             // 0..127
            int kk = (idx & 3) * 4;       // 0,4,8,12
            int r = row0 + m;
            float4 v = make_float4(0.f, 0.f, 0.f, 0.f);
            if (r < NN) v = *(const float4*)(A + (size_t)r * 128 + k0 + kk);
            As[kk + 0][m] = v.x; As[kk + 1][m] = v.y;
            As[kk + 2][m] = v.z; As[kk + 3][m] = v.w;
        }
        // load B tile (16 k x 128 n)
        #pragma unroll
        for (int l = 0; l < 2; l++) {
            int idx = tid + l * 256;
            int k = idx >> 5;             // 0..15
            int n = (idx & 31) * 4;
            *(float4*)(&Bs[k][n]) = *(const float4*)(B + (size_t)(k0 + k) * 128 + n);
        }
        __syncthreads();
        #pragma unroll
        for (int k = 0; k < BK; k++) {
            float a[8], bb[8];
            *(float4*)(a)      = *(const float4*)(&As[k][ty * 8]);
            *(float4*)(a + 4)  = *(const float4*)(&As[k][ty * 8 + 4]);
            *(float4*)(bb)     = *(const float4*)(&Bs[k][tx * 8]);
            *(float4*)(bb + 4) = *(const float4*)(&Bs[k][tx * 8 + 4]);
            #pragma unroll
            for (int i = 0; i < 8; i++)
                #pragma unroll
                for (int j = 0; j < 8; j++)
                    acc[i][j] = fmaf(a[i], bb[j], acc[i][j]);
        }
        __syncthreads();
    }

    float bv[8];
    *(float4*)(bv)     = *(const float4*)(bias + tx * 8);
    *(float4*)(bv + 4) = *(const float4*)(bias + tx * 8 + 4);
    #pragma unroll
    for (int i = 0; i < 8; i++) {
        int r = row0 + ty * 8 + i;
        if (r < NN) {
            float4 o0, o1;
            o0.x = fmaxf(acc[i][0] + bv[0], 0.f);
            o0.y = fmaxf(acc[i][1] + bv[1], 0.f);
            o0.z = fmaxf(acc[i][2] + bv[2], 0.f);
            o0.w = fmaxf(acc[i][3] + bv[3], 0.f);
            o1.x = fmaxf(acc[i][4] + bv[4], 0.f);
            o1.y = fmaxf(acc[i][5] + bv[5], 0.f);
            o1.z = fmaxf(acc[i][6] + bv[6], 0.f);
            o1.w = fmaxf(acc[i][7] + bv[7], 0.f);
            *(float4*)(Cout + (size_t)r * 128 + tx * 8)     = o0;
            *(float4*)(Cout + (size_t)r * 128 + tx * 8 + 4) = o1;
        }
    }
}

// ---------------- K6b: pool Agg(h) per graph (batch is sorted) ----------------
#define POOL_CHUNK 256
__global__ void __launch_bounds__(128) pool_kernel(const float* __restrict__ ha,
                                                   const void* __restrict__ batch) {
    int t = threadIdx.x;           // column 0..127
    int n0 = blockIdx.x * POOL_CHUNK;
    if (n0 >= NN) return;
    int is64 = g_is64;
    int n1 = n0 + POOL_CHUNK; if (n1 > NN) n1 = NN;
    int cur = load_idx(batch, n0, is64) & (GG - 1);
    float acc = 0.f, cacc = 0.f;
    for (int n = n0; n < n1; n++) {
        int g = load_idx(batch, n, is64) & (GG - 1);   // clamp to [0,64)
        if (g != cur) {
            atomicAdd(&g_sums[cur * HH + t], acc);
            if (t == 0) atomicAdd(&g_cnt[cur], cacc);
            acc = 0.f; cacc = 0.f; cur = g;
        }
        acc += ha[(size_t)n * 128 + t];
        cacc += 1.f;
    }
    atomicAdd(&g_sums[cur * HH + t], acc);
    if (t == 0) atomicAdd(&g_cnt[cur], cacc);
}

// ---------------- K7a: fold head weights  Wc = W2@Wlin, bc = b2@Wlin + blin ----
__global__ void combine_kernel(const float* __restrict__ W2, const float* __restrict__ b2,
                               const float* __restrict__ Wlin, const float* __restrict__ blin) {
    int k = threadIdx.x;           // 0..127
    #pragma unroll
    for (int c = 0; c < CC; c++) {
        float s = 0.f;
        for (int j = 0; j < HH; j++) s = fmaf(W2[k * HH + j], Wlin[j * CC + c], s);
        g_Wc[k * CC + c] = s;
    }
    if (k < CC) {
        float s = blin[k];
        for (int j = 0; j < HH; j++) s = fmaf(b2[j], Wlin[j * CC + k], s);
        g_bc[k] = s;
    }
}

// ---------------- K7b: logits = (sums/cnt) @ Wc + bc ----------------
__global__ void final_kernel(float* __restrict__ out) {
    int g = blockIdx.x;            // 0..63
    int warp = threadIdx.x >> 5;   // 0..9 (one warp per class)
    int lane = threadIdx.x & 31;
    float inv = 1.f / fmaxf(g_cnt[g], 1.f);
    if (warp < CC) {
        float s = 0.f;
        for (int k = lane; k < HH; k += 32)
            s = fmaf(g_sums[g * HH + k] * inv, g_Wc[k * CC + warp], s);
        #pragma unroll
        for (int o = 16; o > 0; o >>= 1) s += __shfl_down_sync(0xffffffffu, s, o);
        if (lane == 0) out[g * CC + warp] = s + g_bc[warp];
    }
}

// ---------------- host launch ----------------
extern "C" void kernel_launch(void* const* d_in, const int* in_sizes, int n_in,
                              void* d_out, int out_size) {
    const float* x    = (const float*)d_in[0];
    const float* W1   = (const float*)d_in[1];
    const float* b1   = (const float*)d_in[2];
    const float* W2   = (const float*)d_in[3];
    const float* b2   = (const float*)d_in[4];
    const float* Wlin = (const float*)d_in[5];
    const float* blin = (const float*)d_in[6];
    const void*  ei   = d_in[7];   // edge_index: int32 or int64, detected on device
    const void*  bt   = d_in[8];   // batch: same index dtype
    float* out = (float*)d_out;

    void* p;
    cudaGetSymbolAddress(&p, g_bufA); float* bufA = (float*)p;
    cudaGetSymbolAddress(&p, g_bufB); float* bufB = (float*)p;

    detect_kernel<<<1, 256>>>(ei);
    zero_kernel<<<(NN + 255) / 256, 256>>>();
    deg_kernel<<<(EE + 255) / 256, 256>>>(ei);
    scan_kernel<<<1, 1024>>>();
    fill_kernel<<<(EE + 255) / 256, 256>>>(ei);

    // layer 1: xa = Agg(x); h = relu(xa @ W1 + b1)
    agg_kernel<<<(NN + 7) / 8, 256>>>(x, bufA);
    gemm_bias_relu<<<(NN + 127) / 128, 256>>>(bufA, W1, b1, bufB);

    // layer 2 folded: ha = Agg(h); pool; head on 64x128
    agg_kernel<<<(NN + 7) / 8, 256>>>(bufB, bufA);
    pool_kernel<<<(NN + POOL_CHUNK - 1) / POOL_CHUNK, 128>>>(bufA, bt);
    combine_kernel<<<1, 128>>>(W2, b2, Wlin, blin);
    final_kernel<<<GG, 320>>>(out);
}

// round 6
// speedup vs baseline: 1.6871x; 1.6871x over previous
#include <cuda_runtime.h>
#include <cuda_bf16.h>

// Problem constants (match reference)
#define NN 50000
#define EE 600000
#define GG 64
#define HH 128
#define CC 10

#define SCAN_T 256
#define SCAN_NB ((NN + SCAN_T - 1) / SCAN_T)   // 196

// ---------------- scratch (static device globals; no runtime alloc) ----------------
__device__ int   g_is64;           // 1 if index tensors are int64, 0 if int32
__device__ int   g_deg[NN];        // in-degree (without self loop)
__device__ int   g_off[NN];        // CSR exclusive offsets
__device__ int   g_fill[NN];       // CSR fill cursors
__device__ float g_dinv[NN];       // rsqrt(deg+1)
__device__ int   g_scan[NN];       // block-local inclusive scan of deg
__device__ int   g_bsum[SCAN_NB];  // per-block degree totals
__device__ int   g_bbase[SCAN_NB]; // exclusive scan of block totals
__device__ int2  g_csr[EE];        // {src, bits(dinv[src])} grouped by dst
__device__ float g_bufA[NN * HH];  // xa  (then reused for Agg(h))
__device__ float g_bufB[NN * HH];  // h = relu(xa@W1+b1)
__device__ float g_sums[GG * HH];  // per-graph feature sums
__device__ float g_cnt[GG];        // per-graph node counts
__device__ float g_Wc[HH * CC];    // W2 @ Wlin
__device__ float g_bc[CC];         // b2 @ Wlin + blin

// ---------------- index load helper (dtype-agnostic) ----------------
__device__ __forceinline__ int load_idx(const void* p, long long i, int is64) {
    if (is64) return (int)(((const long long*)p)[i]);
    return ((const int*)p)[i];
}

// ---------------- K_detect: decide int32 vs int64 for index tensors ------------
__global__ void detect_kernel(const void* ei) {
    __shared__ int bad;
    if (threadIdx.x == 0) bad = 0;
    __syncthreads();
    const long long* p = (const long long*)ei;
    for (int i = threadIdx.x; i < 4096; i += blockDim.x) {
        long long v = p[i];   // safe: buffer is >= 2.4MB in either dtype
        if (v < 0 || v >= (long long)NN) bad = 1;
    }
    __syncthreads();
    if (threadIdx.x == 0) g_is64 = bad ? 0 : 1;
}

// ---------------- K0: zero scratch used with atomics ----------------
__global__ void zero_kernel() {
    int i = blockIdx.x * blockDim.x + threadIdx.x;
    if (i < NN) { g_deg[i] = 0; g_fill[i] = 0; }
    if (i < GG * HH) g_sums[i] = 0.f;
    if (i < GG) g_cnt[i] = 0.f;
}

// ---------------- K1: count in-degrees ----------------
__global__ void deg_kernel(const void* __restrict__ ei) {
    int e = blockIdx.x * blockDim.x + threadIdx.x;
    if (e < EE) {
        int is64 = g_is64;
        int dst = load_idx(ei, (long long)EE + e, is64);
        dst = min(max(dst, 0), NN - 1);      // clamp: never crash
        atomicAdd(&g_deg[dst], 1);
    }
}

// ---------------- K2a: per-block inclusive scan of deg + dinv ----------------
__global__ void __launch_bounds__(SCAN_T) scan1_kernel() {
    __shared__ int sh[SCAN_T];
    int b = blockIdx.x, t = threadIdx.x;
    int i = b * SCAN_T + t;
    int v = (i < NN) ? g_deg[i] : 0;
    if (i < NN) g_dinv[i] = rsqrtf((float)(v + 1));
    sh[t] = v;
    __syncthreads();
    #pragma unroll
    for (int s = 1; s < SCAN_T; s <<= 1) {
        int u = (t >= s) ? sh[t - s] : 0;
        __syncthreads();
        sh[t] += u;
        __syncthreads();
    }
    if (i < NN) g_scan[i] = sh[t];               // inclusive within block
    if (t == SCAN_T - 1) g_bsum[b] = sh[t];
}

// ---------------- K2b: exclusive scan of the 196 block totals ----------------
__global__ void __launch_bounds__(SCAN_T) scan2_kernel() {
    __shared__ int sh[SCAN_T];
    int t = threadIdx.x;
    sh[t] = (t < SCAN_NB) ? g_bsum[t] : 0;
    __syncthreads();
    #pragma unroll
    for (int s = 1; s < SCAN_T; s <<= 1) {
        int u = (t >= s) ? sh[t - s] : 0;
        __syncthreads();
        sh[t] += u;
        __syncthreads();
    }
    if (t < SCAN_NB) g_bbase[t] = sh[t] - g_bsum[t];   // exclusive
}

// ---------------- K2c: global exclusive offsets ----------------
__global__ void __launch_bounds__(SCAN_T) scan3_kernel() {
    int b = blockIdx.x, t = threadIdx.x;
    int i = b * SCAN_T + t;
    if (i < NN) g_off[i] = g_bbase[b] + g_scan[i] - g_deg[i];
}

// ---------------- K3: scatter edges into dst-grouped CSR ----------------
__global__ void fill_kernel(const void* __restrict__ ei) {
    int e = blockIdx.x * blockDim.x + threadIdx.x;
    if (e < EE) {
        int is64 = g_is64;
        int src = load_idx(ei, e, is64);
        int dst = load_idx(ei, (long long)EE + e, is64);
        src = min(max(src, 0), NN - 1);
        dst = min(max(dst, 0), NN - 1);
        int pos = g_off[dst] + atomicAdd(&g_fill[dst], 1);
        g_csr[pos] = make_int2(src, __float_as_int(g_dinv[src]));
    }
}

// ---------------- K4/K6: aggregation (warp per dst node, float4 per lane) ----------
__device__ __forceinline__ void fma4(float4& a, float w, const float4& v) {
    a.x = fmaf(w, v.x, a.x); a.y = fmaf(w, v.y, a.y);
    a.z = fmaf(w, v.z, a.z); a.w = fmaf(w, v.w, a.w);
}

__global__ void __launch_bounds__(256) agg_kernel(const float* __restrict__ in,
                                                  float* __restrict__ out) {
    int warp = (blockIdx.x * blockDim.x + threadIdx.x) >> 5;
    int lane = threadIdx.x & 31;
    if (warp >= NN) return;
    int dst = warp;
    float di = g_dinv[dst];
    const float4* sf = (const float4*)in;

    // self-loop term: dinv[dst] * x[dst] inside the sum
    float4 a0 = sf[dst * 32 + lane];
    a0.x *= di; a0.y *= di; a0.z *= di; a0.w *= di;
    float4 a1 = make_float4(0.f, 0.f, 0.f, 0.f);
    float4 a2 = make_float4(0.f, 0.f, 0.f, 0.f);
    float4 a3 = make_float4(0.f, 0.f, 0.f, 0.f);

    int e = g_off[dst];
    int end = e + g_deg[dst];
    // 4-way unroll: 4 independent row loads in flight
    for (; e + 3 < end; e += 4) {
        int2 e0 = g_csr[e + 0];
        int2 e1 = g_csr[e + 1];
        int2 e2 = g_csr[e + 2];
        int2 e3 = g_csr[e + 3];
        float4 v0 = sf[e0.x * 32 + lane];
        float4 v1 = sf[e1.x * 32 + lane];
        float4 v2 = sf[e2.x * 32 + lane];
        float4 v3 = sf[e3.x * 32 + lane];
        fma4(a0, __int_as_float(e0.y), v0);
        fma4(a1, __int_as_float(e1.y), v1);
        fma4(a2, __int_as_float(e2.y), v2);
        fma4(a3, __int_as_float(e3.y), v3);
    }
    for (; e < end; e++) {
        int2 en = g_csr[e];
        float4 v = sf[en.x * 32 + lane];
        fma4(a0, __int_as_float(en.y), v);
    }
    a0.x += a1.x + a2.x + a3.x;
    a0.y += a1.y + a2.y + a3.y;
    a0.z += a1.z + a2.z + a3.z;
    a0.w += a1.w + a2.w + a3.w;
    a0.x *= di; a0.y *= di; a0.z *= di; a0.w *= di;
    ((float4*)out)[dst * 32 + lane] = a0;
}

// ---------------- K5: fused SGEMM  h = relu(xa @ W1 + b1) ----------------
// M=NN, N=128, K=128.  Block 128x128, BK=16, 256 threads, 8x8 per thread.
__global__ void __launch_bounds__(256) gemm_bias_relu(const float* __restrict__ A,
                                                      const float* __restrict__ B,
                                                      const float* __restrict__ bias,
                                                      float* __restrict__ Cout) {
    const int BK = 16;
    __shared__ float As[BK][128];
    __shared__ float Bs[BK][128];
    int tid = threadIdx.x;
    int row0 = blockIdx.x * 128;
    int tx = tid & 15;   // col group (8 cols)
    int ty = tid >> 4;   // row group (8 rows)
    float acc[8][8];
    #pragma unroll
    for (int i = 0; i < 8; i++)
        #pragma unroll
        for (int j = 0; j < 8; j++) acc[i][j] = 0.f;

    for (int k0 = 0; k0 < 128; k0 += BK) {
        // load A tile (128 rows x 16 k), transposed into As[k][m]
        #pragma unroll
        for (int l = 0; l < 2; l++) {
            int idx = tid + l * 256;      // float4 slot 0..511
            int m = idx >> 2;             // 0..127
            int kk = (idx & 3) * 4;       // 0,4,8,12
            int r = row0 + m;
            float4 v = make_float4(0.f, 0.f, 0.f, 0.f);
            if (r < NN) v = *(const float4*)(A + (size_t)r * 128 + k0 + kk);
            As[kk + 0][m] = v.x; As[kk + 1][m] = v.y;
            As[kk + 2][m] = v.z; As[kk + 3][m] = v.w;
        }
        // load B tile (16 k x 128 n)
        #pragma unroll
        for (int l = 0; l < 2; l++) {
            int idx = tid + l * 256;
            int k = idx >> 5;             // 0..15
            int n = (idx & 31) * 4;
            *(float4*)(&Bs[k][n]) = *(const float4*)(B + (size_t)(k0 + k) * 128 + n);
        }
        __syncthreads();
        #pragma unroll
        for (int k = 0; k < BK; k++) {
            float a[8], bb[8];
            *(float4*)(a)      = *(const float4*)(&As[k][ty * 8]);
            *(float4*)(a + 4)  = *(const float4*)(&As[k][ty * 8 + 4]);
            *(float4*)(bb)     = *(const float4*)(&Bs[k][tx * 8]);
            *(float4*)(bb + 4) = *(const float4*)(&Bs[k][tx * 8 + 4]);
            #pragma unroll
            for (int i = 0; i < 8; i++)
                #pragma unroll
                for (int j = 0; j < 8; j++)
                    acc[i][j] = fmaf(a[i], bb[j], acc[i][j]);
        }
        __syncthreads();
    }

    float bv[8];
    *(float4*)(bv)     = *(const float4*)(bias + tx * 8);
    *(float4*)(bv + 4) = *(const float4*)(bias + tx * 8 + 4);
    #pragma unroll
    for (int i = 0; i < 8; i++) {
        int r = row0 + ty * 8 + i;
        if (r < NN) {
            float4 o0, o1;
            o0.x = fmaxf(acc[i][0] + bv[0], 0.f);
            o0.y = fmaxf(acc[i][1] + bv[1], 0.f);
            o0.z = fmaxf(acc[i][2] + bv[2], 0.f);
            o0.w = fmaxf(acc[i][3] + bv[3], 0.f);
            o1.x = fmaxf(acc[i][4] + bv[4], 0.f);
            o1.y = fmaxf(acc[i][5] + bv[5], 0.f);
            o1.z = fmaxf(acc[i][6] + bv[6], 0.f);
            o1.w = fmaxf(acc[i][7] + bv[7], 0.f);
            *(float4*)(Cout + (size_t)r * 128 + tx * 8)     = o0;
            *(float4*)(Cout + (size_t)r * 128 + tx * 8 + 4) = o1;
        }
    }
}

// ---------------- K6b: pool Agg(h) per graph (batch is sorted) ----------------
#define POOL_CHUNK 256
__global__ void __launch_bounds__(128) pool_kernel(const float* __restrict__ ha,
                                                   const void* __restrict__ batch) {
    int t = threadIdx.x;           // column 0..127
    int n0 = blockIdx.x * POOL_CHUNK;
    if (n0 >= NN) return;
    int is64 = g_is64;
    int n1 = n0 + POOL_CHUNK; if (n1 > NN) n1 = NN;
    int cur = load_idx(batch, n0, is64) & (GG - 1);
    float acc = 0.f, cacc = 0.f;
    for (int n = n0; n < n1; n++) {
        int g = load_idx(batch, n, is64) & (GG - 1);   // clamp to [0,64)
        if (g != cur) {
            atomicAdd(&g_sums[cur * HH + t], acc);
            if (t == 0) atomicAdd(&g_cnt[cur], cacc);
            acc = 0.f; cacc = 0.f; cur = g;
        }
        acc += ha[(size_t)n * 128 + t];
        cacc += 1.f;
    }
    atomicAdd(&g_sums[cur * HH + t], acc);
    if (t == 0) atomicAdd(&g_cnt[cur], cacc);
}

// ---------------- K7a: fold head weights  Wc = W2@Wlin, bc = b2@Wlin + blin ----
// grid = CC blocks, 128 threads: block c computes column c of Wc.
__global__ void combine_kernel(const float* __restrict__ W2, const float* __restrict__ b2,
                               const float* __restrict__ Wlin, const float* __restrict__ blin) {
    __shared__ float wl[HH];
    int c = blockIdx.x;
    int k = threadIdx.x;           // 0..127
    wl[k] = Wlin[k * CC + c];
    __syncthreads();
    float s = 0.f;
    #pragma unroll 8
    for (int j = 0; j < HH; j++) s = fmaf(W2[k * HH + j], wl[j], s);
    g_Wc[k * CC + c] = s;
    if (k == 0) {
        float sb = blin[c];
        for (int j = 0; j < HH; j++) sb = fmaf(b2[j], wl[j], sb);
        g_bc[c] = sb;
    }
}

// ---------------- K7b: logits = (sums/cnt) @ Wc + bc ----------------
__global__ void final_kernel(float* __restrict__ out) {
    int g = blockIdx.x;            // 0..63
    int warp = threadIdx.x >> 5;   // 0..9 (one warp per class)
    int lane = threadIdx.x & 31;
    float inv = 1.f / fmaxf(g_cnt[g], 1.f);
    if (warp < CC) {
        float s = 0.f;
        for (int k = lane; k < HH; k += 32)
            s = fmaf(g_sums[g * HH + k] * inv, g_Wc[k * CC + warp], s);
        #pragma unroll
        for (int o = 16; o > 0; o >>= 1) s += __shfl_down_sync(0xffffffffu, s, o);
        if (lane == 0) out[g * CC + warp] = s + g_bc[warp];
    }
}

// ---------------- host launch ----------------
extern "C" void kernel_launch(void* const* d_in, const int* in_sizes, int n_in,
                              void* d_out, int out_size) {
    const float* x    = (const float*)d_in[0];
    const float* W1   = (const float*)d_in[1];
    const float* b1   = (const float*)d_in[2];
    const float* W2   = (const float*)d_in[3];
    const float* b2   = (const float*)d_in[4];
    const float* Wlin = (const float*)d_in[5];
    const float* blin = (const float*)d_in[6];
    const void*  ei   = d_in[7];   // edge_index: int32 or int64, detected on device
    const void*  bt   = d_in[8];   // batch: same index dtype
    float* out = (float*)d_out;

    void* p;
    cudaGetSymbolAddress(&p, g_bufA); float* bufA = (float*)p;
    cudaGetSymbolAddress(&p, g_bufB); float* bufB = (float*)p;

    detect_kernel<<<1, 256>>>(ei);
    zero_kernel<<<(NN + 255) / 256, 256>>>();
    deg_kernel<<<(EE + 255) / 256, 256>>>(ei);
    scan1_kernel<<<SCAN_NB, SCAN_T>>>();
    scan2_kernel<<<1, SCAN_T>>>();
    scan3_kernel<<<SCAN_NB, SCAN_T>>>();
    fill_kernel<<<(EE + 255) / 256, 256>>>(ei);

    // layer 1: xa = Agg(x); h = relu(xa @ W1 + b1)
    agg_kernel<<<(NN + 7) / 8, 256>>>(x, bufA);
    gemm_bias_relu<<<(NN + 127) / 128, 256>>>(bufA, W1, b1, bufB);

    // layer 2 folded: ha = Agg(h); pool; head on 64x128
    agg_kernel<<<(NN + 7) / 8, 256>>>(bufB, bufA);
    pool_kernel<<<(NN + POOL_CHUNK - 1) / POOL_CHUNK, 128>>>(bufA, bt);
    combine_kernel<<<CC, 128>>>(W2, b2, Wlin, blin);
    final_kernel<<<GG, 320>>>(out);
}

// round 7
// speedup vs baseline: 1.9680x; 1.1665x over previous
#include <cuda_runtime.h>
#include <cuda_bf16.h>

// Problem constants (match reference)
#define NN 50000
#define EE 600000
#define GG 64
#define HH 128
#define CC 10

#define SCAN_T 256
#define SCAN_NB ((NN + SCAN_T - 1) / SCAN_T)   // 196

// ---------------- scratch (static device globals; no runtime alloc) ----------------
__device__ int   g_is64;           // 1 if index tensors are int64, 0 if int32
__device__ int   g_deg[NN];        // in-degree (without self loop)
__device__ int   g_off[NN];        // CSR exclusive offsets
__device__ int   g_fill[NN];       // CSR fill cursors
__device__ float g_dinv[NN];       // rsqrt(deg+1)
__device__ int   g_scan[NN];       // block-local inclusive scan of deg
__device__ int   g_bsum[SCAN_NB];  // per-block degree totals
__device__ int   g_bbase[SCAN_NB]; // exclusive scan of block totals
__device__ int2  g_csr[EE];        // {src, bits(dinv[src])} grouped by dst
__device__ float g_bufB[NN * HH];  // h = relu(Agg(x)@W1+b1)
__device__ float g_sums[GG * HH];  // per-graph feature sums
__device__ float g_cnt[GG];        // per-graph node counts
__device__ float g_Wc[HH * CC];    // W2 @ Wlin
__device__ float g_bc[CC];         // b2 @ Wlin + blin

// ---------------- index load helper (dtype-agnostic) ----------------
__device__ __forceinline__ int load_idx(const void* p, long long i, int is64) {
    if (is64) return (int)(((const long long*)p)[i]);
    return ((const int*)p)[i];
}

// ---------------- K_detect: decide int32 vs int64 for index tensors ------------
__global__ void detect_kernel(const void* ei) {
    __shared__ int bad;
    if (threadIdx.x == 0) bad = 0;
    __syncthreads();
    const long long* p = (const long long*)ei;
    for (int i = threadIdx.x; i < 4096; i += blockDim.x) {
        long long v = p[i];   // safe: buffer is >= 2.4MB in either dtype
        if (v < 0 || v >= (long long)NN) bad = 1;
    }
    __syncthreads();
    if (threadIdx.x == 0) g_is64 = bad ? 0 : 1;
}

// ---------------- K0: zero scratch used with atomics ----------------
__global__ void zero_kernel() {
    int i = blockIdx.x * blockDim.x + threadIdx.x;
    if (i < NN) { g_deg[i] = 0; g_fill[i] = 0; }
    if (i < GG * HH) g_sums[i] = 0.f;
    if (i < GG) g_cnt[i] = 0.f;
}

// ---------------- K1: count in-degrees ----------------
__global__ void deg_kernel(const void* __restrict__ ei) {
    int e = blockIdx.x * blockDim.x + threadIdx.x;
    if (e < EE) {
        int is64 = g_is64;
        int dst = load_idx(ei, (long long)EE + e, is64);
        dst = min(max(dst, 0), NN - 1);      // clamp: never crash
        atomicAdd(&g_deg[dst], 1);
    }
}

// ---------------- K2a: per-block inclusive scan of deg + dinv ----------------
__global__ void __launch_bounds__(SCAN_T) scan1_kernel() {
    __shared__ int sh[SCAN_T];
    int b = blockIdx.x, t = threadIdx.x;
    int i = b * SCAN_T + t;
    int v = (i < NN) ? g_deg[i] : 0;
    if (i < NN) g_dinv[i] = rsqrtf((float)(v + 1));
    sh[t] = v;
    __syncthreads();
    #pragma unroll
    for (int s = 1; s < SCAN_T; s <<= 1) {
        int u = (t >= s) ? sh[t - s] : 0;
        __syncthreads();
        sh[t] += u;
        __syncthreads();
    }
    if (i < NN) g_scan[i] = sh[t];               // inclusive within block
    if (t == SCAN_T - 1) g_bsum[b] = sh[t];
}

// ---------------- K2b: exclusive scan of the 196 block totals ----------------
__global__ void __launch_bounds__(SCAN_T) scan2_kernel() {
    __shared__ int sh[SCAN_T];
    int t = threadIdx.x;
    sh[t] = (t < SCAN_NB) ? g_bsum[t] : 0;
    __syncthreads();
    #pragma unroll
    for (int s = 1; s < SCAN_T; s <<= 1) {
        int u = (t >= s) ? sh[t - s] : 0;
        __syncthreads();
        sh[t] += u;
        __syncthreads();
    }
    if (t < SCAN_NB) g_bbase[t] = sh[t] - g_bsum[t];   // exclusive
}

// ---------------- K2c: global exclusive offsets ----------------
__global__ void __launch_bounds__(SCAN_T) scan3_kernel() {
    int b = blockIdx.x, t = threadIdx.x;
    int i = b * SCAN_T + t;
    if (i < NN) g_off[i] = g_bbase[b] + g_scan[i] - g_deg[i];
}

// ---------------- K3: scatter edges into dst-grouped CSR ----------------
__global__ void fill_kernel(const void* __restrict__ ei) {
    int e = blockIdx.x * blockDim.x + threadIdx.x;
    if (e < EE) {
        int is64 = g_is64;
        int src = load_idx(ei, e, is64);
        int dst = load_idx(ei, (long long)EE + e, is64);
        src = min(max(src, 0), NN - 1);
        dst = min(max(dst, 0), NN - 1);
        int pos = g_off[dst] + atomicAdd(&g_fill[dst], 1);
        g_csr[pos] = make_int2(src, __float_as_int(g_dinv[src]));
    }
}

// ---------------- shared agg helper: one warp aggregates one dst row ----------
__device__ __forceinline__ void fma4(float4& a, float w, const float4& v) {
    a.x = fmaf(w, v.x, a.x); a.y = fmaf(w, v.y, a.y);
    a.z = fmaf(w, v.z, a.z); a.w = fmaf(w, v.w, a.w);
}

__device__ __forceinline__ float4 agg_row(const float4* __restrict__ sf, int dst, int lane) {
    float di = g_dinv[dst];
    float4 a0 = sf[dst * 32 + lane];          // self loop
    a0.x *= di; a0.y *= di; a0.z *= di; a0.w *= di;
    float4 a1 = make_float4(0.f, 0.f, 0.f, 0.f);
    float4 a2 = make_float4(0.f, 0.f, 0.f, 0.f);
    float4 a3 = make_float4(0.f, 0.f, 0.f, 0.f);
    int e = g_off[dst];
    int end = e + g_deg[dst];
    for (; e + 3 < end; e += 4) {
        int2 e0 = g_csr[e + 0];
        int2 e1 = g_csr[e + 1];
        int2 e2 = g_csr[e + 2];
        int2 e3 = g_csr[e + 3];
        float4 v0 = sf[e0.x * 32 + lane];
        float4 v1 = sf[e1.x * 32 + lane];
        float4 v2 = sf[e2.x * 32 + lane];
        float4 v3 = sf[e3.x * 32 + lane];
        fma4(a0, __int_as_float(e0.y), v0);
        fma4(a1, __int_as_float(e1.y), v1);
        fma4(a2, __int_as_float(e2.y), v2);
        fma4(a3, __int_as_float(e3.y), v3);
    }
    for (; e < end; e++) {
        int2 en = g_csr[e];
        float4 v = sf[en.x * 32 + lane];
        fma4(a0, __int_as_float(en.y), v);
    }
    a0.x += a1.x + a2.x + a3.x;
    a0.y += a1.y + a2.y + a3.y;
    a0.z += a1.z + a2.z + a3.z;
    a0.w += a1.w + a2.w + a3.w;
    a0.x *= di; a0.y *= di; a0.z *= di; a0.w *= di;
    return a0;
}

// ---------------- K4: FUSED  h = relu(Agg(x) @ W1 + b1)  -----------------------
// Block = 128 output rows. Phase 1: 8 warps aggregate 128 rows into smem As
// (row-major). Phase 2: classic 128x128 SGEMM from smem. 72KB dyn smem, 2 CTA/SM.
#define GM_BK 16
__global__ void __launch_bounds__(256, 2) fused_agg_gemm(const float* __restrict__ x,
                                                         const float* __restrict__ B,
                                                         const float* __restrict__ bias,
                                                         float* __restrict__ Cout) {
    extern __shared__ float smf[];
    float* As = smf;                 // 128 x 128 row-major (64KB)
    float* Bs = smf + 128 * 128;     // GM_BK x 128        (8KB)
    int tid = threadIdx.x;
    int wid = tid >> 5, lane = tid & 31;
    int row0 = blockIdx.x * 128;
    const float4* sf = (const float4*)x;

    // ---- phase 1: aggregate this block's 128 rows into As ----
    #pragma unroll 1
    for (int r = 0; r < 16; r++) {
        int m = wid * 16 + r;
        int dst = row0 + m;
        float4 a0 = make_float4(0.f, 0.f, 0.f, 0.f);
        if (dst < NN) a0 = agg_row(sf, dst, lane);
        *(float4*)(As + m * 128 + lane * 4) = a0;
    }
    __syncthreads();

    // ---- phase 2: GEMM: C[m][n] = sum_k As[m][k] * B[k][n] ----
    int tx = tid & 15;   // col group (8 cols)
    int ty = tid >> 4;   // row group (8 rows)
    float acc[8][8];
    #pragma unroll
    for (int i = 0; i < 8; i++)
        #pragma unroll
        for (int j = 0; j < 8; j++) acc[i][j] = 0.f;

    for (int k0 = 0; k0 < 128; k0 += GM_BK) {
        // load B tile (16 k x 128 n): 512 float4 slots over 256 threads
        #pragma unroll
        for (int l = 0; l < 2; l++) {
            int idx = tid + l * 256;
            int k = idx >> 5;
            int n = (idx & 31) * 4;
            *(float4*)(Bs + k * 128 + n) = *(const float4*)(B + (size_t)(k0 + k) * 128 + n);
        }
        __syncthreads();
        #pragma unroll
        for (int k = 0; k < GM_BK; k++) {
            float a[8], bb[8];
            #pragma unroll
            for (int i = 0; i < 8; i++) a[i] = As[(ty * 8 + i) * 128 + k0 + k];
            *(float4*)(bb)     = *(const float4*)(Bs + k * 128 + tx * 8);
            *(float4*)(bb + 4) = *(const float4*)(Bs + k * 128 + tx * 8 + 4);
            #pragma unroll
            for (int i = 0; i < 8; i++)
                #pragma unroll
                for (int j = 0; j < 8; j++)
                    acc[i][j] = fmaf(a[i], bb[j], acc[i][j]);
        }
        __syncthreads();
    }

    float bv[8];
    *(float4*)(bv)     = *(const float4*)(bias + tx * 8);
    *(float4*)(bv + 4) = *(const float4*)(bias + tx * 8 + 4);
    #pragma unroll
    for (int i = 0; i < 8; i++) {
        int r = row0 + ty * 8 + i;
        if (r < NN) {
            float4 o0, o1;
            o0.x = fmaxf(acc[i][0] + bv[0], 0.f);
            o0.y = fmaxf(acc[i][1] + bv[1], 0.f);
            o0.z = fmaxf(acc[i][2] + bv[2], 0.f);
            o0.w = fmaxf(acc[i][3] + bv[3], 0.f);
            o1.x = fmaxf(acc[i][4] + bv[4], 0.f);
            o1.y = fmaxf(acc[i][5] + bv[5], 0.f);
            o1.z = fmaxf(acc[i][6] + bv[6], 0.f);
            o1.w = fmaxf(acc[i][7] + bv[7], 0.f);
            *(float4*)(Cout + (size_t)r * 128 + tx * 8)     = o0;
            *(float4*)(Cout + (size_t)r * 128 + tx * 8 + 4) = o1;
        }
    }
}

// ---------------- K5: FUSED  Agg(h) + per-graph pool  --------------------------
// Block = 8 consecutive dst nodes (one warp each). Results land in smem, then
// 128 threads flush sorted runs into g_sums with few global atomics.
__global__ void __launch_bounds__(256) agg_pool_kernel(const float* __restrict__ in,
                                                       const void* __restrict__ batch) {
    __shared__ float rows[8][128];
    __shared__ int rowg[8];
    int tid = threadIdx.x;
    int wid = tid >> 5, lane = tid & 31;
    int dst = blockIdx.x * 8 + wid;
    int is64 = g_is64;
    const float4* sf = (const float4*)in;

    if (dst < NN) {
        float4 a0 = agg_row(sf, dst, lane);
        *(float4*)(&rows[wid][lane * 4]) = a0;
        if (lane == 0) rowg[wid] = load_idx(batch, dst, is64) & (GG - 1);
    } else if (lane == 0) {
        rowg[wid] = -1;
    }
    __syncthreads();

    if (tid < 128) {
        int t = tid;
        int cur = rowg[0];
        float acc = 0.f;
        #pragma unroll
        for (int r = 0; r < 8; r++) {
            int g = rowg[r];
            if (g < 0) break;
            if (g != cur) {
                atomicAdd(&g_sums[cur * HH + t], acc);
                acc = 0.f; cur = g;
            }
            acc += rows[r][t];
        }
        if (cur >= 0) atomicAdd(&g_sums[cur * HH + t], acc);
    } else if (tid == 128) {
        int cur = rowg[0];
        float c = 0.f;
        #pragma unroll
        for (int r = 0; r < 8; r++) {
            int g = rowg[r];
            if (g < 0) break;
            if (g != cur) { atomicAdd(&g_cnt[cur], c); c = 0.f; cur = g; }
            c += 1.f;
        }
        if (cur >= 0) atomicAdd(&g_cnt[cur], c);
    }
}

// ---------------- K7a: fold head weights  Wc = W2@Wlin, bc = b2@Wlin + blin ----
__global__ void combine_kernel(const float* __restrict__ W2, const float* __restrict__ b2,
                               const float* __restrict__ Wlin, const float* __restrict__ blin) {
    __shared__ float wl[HH];
    int c = blockIdx.x;
    int k = threadIdx.x;           // 0..127
    wl[k] = Wlin[k * CC + c];
    __syncthreads();
    float s = 0.f;
    #pragma unroll 8
    for (int j = 0; j < HH; j++) s = fmaf(W2[k * HH + j], wl[j], s);
    g_Wc[k * CC + c] = s;
    if (k == 0) {
        float sb = blin[c];
        for (int j = 0; j < HH; j++) sb = fmaf(b2[j], wl[j], sb);
        g_bc[c] = sb;
    }
}

// ---------------- K7b: logits = (sums/cnt) @ Wc + bc ----------------
__global__ void final_kernel(float* __restrict__ out) {
    int g = blockIdx.x;            // 0..63
    int warp = threadIdx.x >> 5;   // 0..9 (one warp per class)
    int lane = threadIdx.x & 31;
    float inv = 1.f / fmaxf(g_cnt[g], 1.f);
    if (warp < CC) {
        float s = 0.f;
        for (int k = lane; k < HH; k += 32)
            s = fmaf(g_sums[g * HH + k] * inv, g_Wc[k * CC + warp], s);
        #pragma unroll
        for (int o = 16; o > 0; o >>= 1) s += __shfl_down_sync(0xffffffffu, s, o);
        if (lane == 0) out[g * CC + warp] = s + g_bc[warp];
    }
}

// ---------------- host launch ----------------
extern "C" void kernel_launch(void* const* d_in, const int* in_sizes, int n_in,
                              void* d_out, int out_size) {
    const float* x    = (const float*)d_in[0];
    const float* W1   = (const float*)d_in[1];
    const float* b1   = (const float*)d_in[2];
    const float* W2   = (const float*)d_in[3];
    const float* b2   = (const float*)d_in[4];
    const float* Wlin = (const float*)d_in[5];
    const float* blin = (const float*)d_in[6];
    const void*  ei   = d_in[7];   // edge_index: int32 or int64, detected on device
    const void*  bt   = d_in[8];   // batch: same index dtype
    float* out = (float*)d_out;

    void* p;
    cudaGetSymbolAddress(&p, g_bufB); float* bufB = (float*)p;

    const int FUSED_SMEM = (128 * 128 + GM_BK * 128) * (int)sizeof(float);  // 72KB
    cudaFuncSetAttribute(fused_agg_gemm, cudaFuncAttributeMaxDynamicSharedMemorySize, FUSED_SMEM);

    detect_kernel<<<1, 256>>>(ei);
    zero_kernel<<<(NN + 255) / 256, 256>>>();
    deg_kernel<<<(EE + 255) / 256, 256>>>(ei);
    scan1_kernel<<<SCAN_NB, SCAN_T>>>();
    scan2_kernel<<<1, SCAN_T>>>();
    scan3_kernel<<<SCAN_NB, SCAN_T>>>();
    fill_kernel<<<(EE + 255) / 256, 256>>>(ei);

    // layer 1 fused: h = relu(Agg(x) @ W1 + b1)
    fused_agg_gemm<<<(NN + 127) / 128, 256, FUSED_SMEM>>>(x, W1, b1, bufB);

    // layer 2 folded + fused: pool(Agg(h)); head on 64x128
    agg_pool_kernel<<<(NN + 7) / 8, 256>>>(bufB, bt);
    combine_kernel<<<CC, 128>>>(W2, b2, Wlin, blin);
    final_kernel<<<GG, 320>>>(out);
}

// round 8
// speedup vs baseline: 1.9976x; 1.0150x over previous
#include <cuda_runtime.h>
#include <cuda_bf16.h>

// Problem constants (match reference)
#define NN 50000
#define EE 600000
#define GG 64
#define HH 128
#define CC 10

#define SCAN_T 256
#define SCAN_NB ((NN + SCAN_T - 1) / SCAN_T)   // 196

typedef unsigned long long u64;

// ---------------- scratch (static device globals; no runtime alloc) ----------------
__device__ int   g_is64;           // 1 if index tensors are int64, 0 if int32
__device__ int   g_deg[NN];        // in-degree (without self loop)
__device__ int   g_off[NN];        // CSR exclusive offsets
__device__ int   g_fill[NN];       // CSR fill cursors
__device__ float g_dinv[NN];       // rsqrt(deg+1)
__device__ int   g_scan[NN];       // block-local inclusive scan of deg
__device__ int   g_bsum[SCAN_NB];  // per-block degree totals
__device__ int   g_bbase[SCAN_NB]; // exclusive scan of block totals
__device__ int2  g_csr[EE];        // {src, bits(dinv[src])} grouped by dst
__device__ float g_bufB[NN * HH];  // h = relu(Agg(x)@W1+b1)
__device__ float g_sums[GG * HH];  // per-graph feature sums
__device__ float g_cnt[GG];        // per-graph node counts
__device__ float g_Wc[HH * CC];    // W2 @ Wlin
__device__ float g_bc[CC];         // b2 @ Wlin + blin

// ---------------- packed f32x2 helpers ----------------
__device__ __forceinline__ u64 pack2_dup(float v) {
    u64 r; asm("mov.b64 %0, {%1, %1};" : "=l"(r) : "f"(v)); return r;
}
__device__ __forceinline__ void ffma2(u64& d, u64 a, u64 b) {
    asm("fma.rn.f32x2 %0, %1, %2, %0;" : "+l"(d) : "l"(a), "l"(b));
}
__device__ __forceinline__ void unpack2(float& lo, float& hi, u64 v) {
    asm("mov.b64 {%0, %1}, %2;" : "=f"(lo), "=f"(hi) : "l"(v));
}

// ---------------- index load helper (dtype-agnostic) ----------------
__device__ __forceinline__ int load_idx(const void* p, long long i, int is64) {
    if (is64) return (int)(((const long long*)p)[i]);
    return ((const int*)p)[i];
}

// ---------------- K_detect: decide int32 vs int64 for index tensors ------------
__global__ void detect_kernel(const void* ei) {
    __shared__ int bad;
    if (threadIdx.x == 0) bad = 0;
    __syncthreads();
    const long long* p = (const long long*)ei;
    for (int i = threadIdx.x; i < 1024; i += blockDim.x) {
        long long v = p[i];
        if (v < 0 || v >= (long long)NN) bad = 1;
    }
    __syncthreads();
    if (threadIdx.x == 0) g_is64 = bad ? 0 : 1;
}

// ---------------- K0: zero scratch used with atomics ----------------
__global__ void zero_kernel() {
    int i = blockIdx.x * blockDim.x + threadIdx.x;
    if (i < NN) { g_deg[i] = 0; g_fill[i] = 0; }
    if (i < GG * HH) g_sums[i] = 0.f;
    if (i < GG) g_cnt[i] = 0.f;
}

// ---------------- K1: count in-degrees ----------------
__global__ void deg_kernel(const void* __restrict__ ei) {
    int e = blockIdx.x * blockDim.x + threadIdx.x;
    if (e < EE) {
        int is64 = g_is64;
        int dst = load_idx(ei, (long long)EE + e, is64);
        dst = min(max(dst, 0), NN - 1);      // clamp: never crash
        atomicAdd(&g_deg[dst], 1);
    }
}

// ---------------- K2a: per-block inclusive scan of deg + dinv ----------------
__global__ void __launch_bounds__(SCAN_T) scan1_kernel() {
    __shared__ int sh[SCAN_T];
    int b = blockIdx.x, t = threadIdx.x;
    int i = b * SCAN_T + t;
    int v = (i < NN) ? g_deg[i] : 0;
    if (i < NN) g_dinv[i] = rsqrtf((float)(v + 1));
    sh[t] = v;
    __syncthreads();
    #pragma unroll
    for (int s = 1; s < SCAN_T; s <<= 1) {
        int u = (t >= s) ? sh[t - s] : 0;
        __syncthreads();
        sh[t] += u;
        __syncthreads();
    }
    if (i < NN) g_scan[i] = sh[t];               // inclusive within block
    if (t == SCAN_T - 1) g_bsum[b] = sh[t];
}

// ---------------- K2b: exclusive scan of the 196 block totals ----------------
__global__ void __launch_bounds__(SCAN_T) scan2_kernel() {
    __shared__ int sh[SCAN_T];
    int t = threadIdx.x;
    sh[t] = (t < SCAN_NB) ? g_bsum[t] : 0;
    __syncthreads();
    #pragma unroll
    for (int s = 1; s < SCAN_T; s <<= 1) {
        int u = (t >= s) ? sh[t - s] : 0;
        __syncthreads();
        sh[t] += u;
        __syncthreads();
    }
    if (t < SCAN_NB) g_bbase[t] = sh[t] - g_bsum[t];   // exclusive
}

// ---------------- K2c: global exclusive offsets ----------------
__global__ void __launch_bounds__(SCAN_T) scan3_kernel() {
    int b = blockIdx.x, t = threadIdx.x;
    int i = b * SCAN_T + t;
    if (i < NN) g_off[i] = g_bbase[b] + g_scan[i] - g_deg[i];
}

// ---------------- K3: scatter edges into dst-grouped CSR ----------------
__global__ void fill_kernel(const void* __restrict__ ei) {
    int e = blockIdx.x * blockDim.x + threadIdx.x;
    if (e < EE) {
        int is64 = g_is64;
        int src = load_idx(ei, e, is64);
        int dst = load_idx(ei, (long long)EE + e, is64);
        src = min(max(src, 0), NN - 1);
        dst = min(max(dst, 0), NN - 1);
        int pos = g_off[dst] + atomicAdd(&g_fill[dst], 1);
        g_csr[pos] = make_int2(src, __float_as_int(g_dinv[src]));
    }
}

// ---------------- shared agg helper: one warp aggregates one dst row ----------
__device__ __forceinline__ void fma4(float4& a, float w, const float4& v) {
    a.x = fmaf(w, v.x, a.x); a.y = fmaf(w, v.y, a.y);
    a.z = fmaf(w, v.z, a.z); a.w = fmaf(w, v.w, a.w);
}

__device__ __forceinline__ float4 agg_row(const float4* __restrict__ sf, int dst, int lane) {
    float di = g_dinv[dst];
    float4 a0 = sf[dst * 32 + lane];          // self loop
    a0.x *= di; a0.y *= di; a0.z *= di; a0.w *= di;
    float4 a1 = make_float4(0.f, 0.f, 0.f, 0.f);
    float4 a2 = make_float4(0.f, 0.f, 0.f, 0.f);
    float4 a3 = make_float4(0.f, 0.f, 0.f, 0.f);
    int e = g_off[dst];
    int end = e + g_deg[dst];
    for (; e + 3 < end; e += 4) {
        int2 e0 = g_csr[e + 0];
        int2 e1 = g_csr[e + 1];
        int2 e2 = g_csr[e + 2];
        int2 e3 = g_csr[e + 3];
        float4 v0 = sf[e0.x * 32 + lane];
        float4 v1 = sf[e1.x * 32 + lane];
        float4 v2 = sf[e2.x * 32 + lane];
        float4 v3 = sf[e3.x * 32 + lane];
        fma4(a0, __int_as_float(e0.y), v0);
        fma4(a1, __int_as_float(e1.y), v1);
        fma4(a2, __int_as_float(e2.y), v2);
        fma4(a3, __int_as_float(e3.y), v3);
    }
    for (; e < end; e++) {
        int2 en = g_csr[e];
        float4 v = sf[en.x * 32 + lane];
        fma4(a0, __int_as_float(en.y), v);
    }
    a0.x += a1.x + a2.x + a3.x;
    a0.y += a1.y + a2.y + a3.y;
    a0.z += a1.z + a2.z + a3.z;
    a0.w += a1.w + a2.w + a3.w;
    a0.x *= di; a0.y *= di; a0.z *= di; a0.w *= di;
    return a0;
}

// ---------------- K4: FUSED  h = relu(Agg(x) @ W1 + b1)  -----------------------
// Block = 128 output rows. Phase 1: 8 warps aggregate 128 rows into smem As
// (row-major). Phase 2: 128x128 SGEMM from smem using packed f32x2 FMA.
#define GM_BK 16
__global__ void __launch_bounds__(256, 2) fused_agg_gemm(const float* __restrict__ x,
                                                         const float* __restrict__ B,
                                                         const float* __restrict__ bias,
                                                         float* __restrict__ Cout) {
    extern __shared__ float smf[];
    float* As = smf;                 // 128 x 128 row-major (64KB)
    float* Bs = smf + 128 * 128;     // GM_BK x 128        (8KB)
    int tid = threadIdx.x;
    int wid = tid >> 5, lane = tid & 31;
    int row0 = blockIdx.x * 128;
    const float4* sf = (const float4*)x;

    // ---- phase 1: aggregate this block's 128 rows into As ----
    #pragma unroll 1
    for (int r = 0; r < 16; r++) {
        int m = wid * 16 + r;
        int dst = row0 + m;
        float4 a0 = make_float4(0.f, 0.f, 0.f, 0.f);
        if (dst < NN) a0 = agg_row(sf, dst, lane);
        *(float4*)(As + m * 128 + lane * 4) = a0;
    }
    __syncthreads();

    // ---- phase 2: GEMM with packed f32x2: C[m][n] = sum_k As[m][k]*B[k][n] ----
    int tx = tid & 15;   // col group (8 cols = 4 pairs)
    int ty = tid >> 4;   // row group (8 rows)
    u64 acc2[8][4];
    #pragma unroll
    for (int i = 0; i < 8; i++)
        #pragma unroll
        for (int j = 0; j < 4; j++) acc2[i][j] = 0ull;

    for (int k0 = 0; k0 < 128; k0 += GM_BK) {
        // load B tile (16 k x 128 n): 512 float4 slots over 256 threads
        #pragma unroll
        for (int l = 0; l < 2; l++) {
            int idx = tid + l * 256;
            int k = idx >> 5;
            int n = (idx & 31) * 4;
            *(float4*)(Bs + k * 128 + n) = *(const float4*)(B + (size_t)(k0 + k) * 128 + n);
        }
        __syncthreads();
        #pragma unroll
        for (int k = 0; k < GM_BK; k++) {
            u64 ap[8];
            #pragma unroll
            for (int i = 0; i < 8; i++)
                ap[i] = pack2_dup(As[(ty * 8 + i) * 128 + k0 + k]);
            const u64* bsp = (const u64*)(Bs + k * 128 + tx * 8);
            u64 bp0 = bsp[0], bp1 = bsp[1], bp2 = bsp[2], bp3 = bsp[3];
            #pragma unroll
            for (int i = 0; i < 8; i++) {
                ffma2(acc2[i][0], ap[i], bp0);
                ffma2(acc2[i][1], ap[i], bp1);
                ffma2(acc2[i][2], ap[i], bp2);
                ffma2(acc2[i][3], ap[i], bp3);
            }
        }
        __syncthreads();
    }

    float bv[8];
    *(float4*)(bv)     = *(const float4*)(bias + tx * 8);
    *(float4*)(bv + 4) = *(const float4*)(bias + tx * 8 + 4);
    #pragma unroll
    for (int i = 0; i < 8; i++) {
        int r = row0 + ty * 8 + i;
        if (r < NN) {
            float o[8];
            #pragma unroll
            for (int j = 0; j < 4; j++) {
                float lo, hi;
                unpack2(lo, hi, acc2[i][j]);
                o[j * 2 + 0] = fmaxf(lo + bv[j * 2 + 0], 0.f);
                o[j * 2 + 1] = fmaxf(hi + bv[j * 2 + 1], 0.f);
            }
            *(float4*)(Cout + (size_t)r * 128 + tx * 8)     = *(float4*)(o);
            *(float4*)(Cout + (size_t)r * 128 + tx * 8 + 4) = *(float4*)(o + 4);
        }
    }
}

// ---------------- K5: FUSED  Agg(h) + per-graph pool  --------------------------
__global__ void __launch_bounds__(256) agg_pool_kernel(const float* __restrict__ in,
                                                       const void* __restrict__ batch) {
    __shared__ float rows[8][128];
    __shared__ int rowg[8];
    int tid = threadIdx.x;
    int wid = tid >> 5, lane = tid & 31;
    int dst = blockIdx.x * 8 + wid;
    int is64 = g_is64;
    const float4* sf = (const float4*)in;

    if (dst < NN) {
        float4 a0 = agg_row(sf, dst, lane);
        *(float4*)(&rows[wid][lane * 4]) = a0;
        if (lane == 0) rowg[wid] = load_idx(batch, dst, is64) & (GG - 1);
    } else if (lane == 0) {
        rowg[wid] = -1;
    }
    __syncthreads();

    if (tid < 128) {
        int t = tid;
        int cur = rowg[0];
        float acc = 0.f;
        #pragma unroll
        for (int r = 0; r < 8; r++) {
            int g = rowg[r];
            if (g < 0) break;
            if (g != cur) {
                atomicAdd(&g_sums[cur * HH + t], acc);
                acc = 0.f; cur = g;
            }
            acc += rows[r][t];
        }
        if (cur >= 0) atomicAdd(&g_sums[cur * HH + t], acc);
    } else if (tid == 128) {
        int cur = rowg[0];
        float c = 0.f;
        #pragma unroll
        for (int r = 0; r < 8; r++) {
            int g = rowg[r];
            if (g < 0) break;
            if (g != cur) { atomicAdd(&g_cnt[cur], c); c = 0.f; cur = g; }
            c += 1.f;
        }
        if (cur >= 0) atomicAdd(&g_cnt[cur], c);
    }
}

// ---------------- K7a: fold head weights  Wc = W2@Wlin, bc = b2@Wlin + blin ----
__global__ void combine_kernel(const float* __restrict__ W2, const float* __restrict__ b2,
                               const float* __restrict__ Wlin, const float* __restrict__ blin) {
    __shared__ float wl[HH];
    int c = blockIdx.x;
    int k = threadIdx.x;           // 0..127
    wl[k] = Wlin[k * CC + c];
    __syncthreads();
    float s = 0.f;
    #pragma unroll 8
    for (int j = 0; j < HH; j++) s = fmaf(W2[k * HH + j], wl[j], s);
    g_Wc[k * CC + c] = s;
    if (k == 0) {
        float sb = blin[c];
        for (int j = 0; j < HH; j++) sb = fmaf(b2[j], wl[j], sb);
        g_bc[c] = sb;
    }
}

// ---------------- K7b: logits = (sums/cnt) @ Wc + bc ----------------
__global__ void final_kernel(float* __restrict__ out) {
    int g = blockIdx.x;            // 0..63
    int warp = threadIdx.x >> 5;   // 0..9 (one warp per class)
    int lane = threadIdx.x & 31;
    float inv = 1.f / fmaxf(g_cnt[g], 1.f);
    if (warp < CC) {
        float s = 0.f;
        for (int k = lane; k < HH; k += 32)
            s = fmaf(g_sums[g * HH + k] * inv, g_Wc[k * CC + warp], s);
        #pragma unroll
        for (int o = 16; o > 0; o >>= 1) s += __shfl_down_sync(0xffffffffu, s, o);
        if (lane == 0) out[g * CC + warp] = s + g_bc[warp];
    }
}

// ---------------- host launch ----------------
extern "C" void kernel_launch(void* const* d_in, const int* in_sizes, int n_in,
                              void* d_out, int out_size) {
    const float* x    = (const float*)d_in[0];
    const float* W1   = (const float*)d_in[1];
    const float* b1   = (const float*)d_in[2];
    const float* W2   = (const float*)d_in[3];
    const float* b2   = (const float*)d_in[4];
    const float* Wlin = (const float*)d_in[5];
    const float* blin = (const float*)d_in[6];
    const void*  ei   = d_in[7];   // edge_index: int32 or int64, detected on device
    const void*  bt   = d_in[8];   // batch: same index dtype
    float* out = (float*)d_out;

    void* p;
    cudaGetSymbolAddress(&p, g_bufB); float* bufB = (float*)p;

    const int FUSED_SMEM = (128 * 128 + GM_BK * 128) * (int)sizeof(float);  // 72KB
    cudaFuncSetAttribute(fused_agg_gemm, cudaFuncAttributeMaxDynamicSharedMemorySize, FUSED_SMEM);

    detect_kernel<<<1, 256>>>(ei);
    zero_kernel<<<(NN + 255) / 256, 256>>>();
    deg_kernel<<<(EE + 255) / 256, 256>>>(ei);
    scan1_kernel<<<SCAN_NB, SCAN_T>>>();
    scan2_kernel<<<1, SCAN_T>>>();
    scan3_kernel<<<SCAN_NB, SCAN_T>>>();
    fill_kernel<<<(EE + 255) / 256, 256>>>(ei);

    // layer 1 fused: h = relu(Agg(x) @ W1 + b1)
    fused_agg_gemm<<<(NN + 127) / 128, 256, FUSED_SMEM>>>(x, W1, b1, bufB);

    // layer 2 folded + fused: pool(Agg(h)); head on 64x128
    agg_pool_kernel<<<(NN + 7) / 8, 256>>>(bufB, bt);
    combine_kernel<<<CC, 128>>>(W2, b2, Wlin, blin);
    final_kernel<<<GG, 320>>>(out);
}

// round 10
// speedup vs baseline: 2.1458x; 1.0742x over previous
#include <cuda_runtime.h>
#include <cuda_bf16.h>

// Problem constants (match reference)
#define NN 50000
#define EE 600000
#define GG 64
#define HH 128
#define CC 10

#define SCAN_T 256
#define SCAN_NB ((NN + SCAN_T - 1) / SCAN_T)   // 196

typedef unsigned long long u64;
typedef unsigned int u32;

// ---------------- scratch (static device globals; no runtime alloc) ----------------
__device__ int   g_is64;           // 1 if index tensors are int64, 0 if int32
__device__ int   g_deg[NN];        // in-degree (without self loop)
__device__ int   g_off[NN];        // CSR exclusive offsets
__device__ int   g_fill[NN];       // CSR fill cursors
__device__ float g_dinv[NN];       // rsqrt(deg+1)
__device__ int   g_scan[NN];       // block-local inclusive scan of deg
__device__ int   g_bsum[SCAN_NB];  // per-block degree totals
__device__ int   g_bbase[SCAN_NB]; // exclusive scan of block totals
__device__ int2  g_csr[EE];        // {src, bits(dinv[src])} grouped by dst
__device__ uint2 g_xbf[NN * 32];   // x in bf16 (row = 32 uint2 = 128 bf16)
__device__ uint2 g_hbf[NN * 32];   // h = relu(Agg(x)@W1+b1) in bf16
__device__ float g_sums[GG * HH];  // per-graph feature sums
__device__ float g_cnt[GG];        // per-graph node counts
__device__ float g_Wc[HH * CC];    // W2 @ Wlin
__device__ float g_bc[CC];         // b2 @ Wlin + blin

// ---------------- packed f32x2 helpers ----------------
__device__ __forceinline__ u64 pack2_dup(float v) {
    u64 r; asm("mov.b64 %0, {%1, %1};" : "=l"(r) : "f"(v)); return r;
}
__device__ __forceinline__ void ffma2(u64& d, u64 a, u64 b) {
    asm("fma.rn.f32x2 %0, %1, %2, %0;" : "+l"(d) : "l"(a), "l"(b));
}
__device__ __forceinline__ void unpack2(float& lo, float& hi, u64 v) {
    asm("mov.b64 {%0, %1}, %2;" : "=f"(lo), "=f"(hi) : "l"(v));
}

// ---------------- bf16 helpers ----------------
__device__ __forceinline__ float4 bf2f4(uint2 v) {
    __nv_bfloat162 p0 = *(__nv_bfloat162*)&v.x;
    __nv_bfloat162 p1 = *(__nv_bfloat162*)&v.y;
    float2 f0 = __bfloat1622float2(p0);
    float2 f1 = __bfloat1622float2(p1);
    return make_float4(f0.x, f0.y, f1.x, f1.y);
}
__device__ __forceinline__ u32 f2bf2(float a, float b) {
    __nv_bfloat162 p = __float22bfloat162_rn(make_float2(a, b));
    return *(u32*)&p;
}

// ---------------- index load helper (dtype-agnostic) ----------------
__device__ __forceinline__ int load_idx(const void* p, long long i, int is64) {
    if (is64) return (int)(((const long long*)p)[i]);
    return ((const int*)p)[i];
}

// ---------------- K_detect ----------------
__global__ void detect_kernel(const void* ei) {
    __shared__ int bad;
    if (threadIdx.x == 0) bad = 0;
    __syncthreads();
    const long long* p = (const long long*)ei;
    for (int i = threadIdx.x; i < 1024; i += blockDim.x) {
        long long v = p[i];
        if (v < 0 || v >= (long long)NN) bad = 1;
    }
    __syncthreads();
    if (threadIdx.x == 0) g_is64 = bad ? 0 : 1;
}

// ---------------- K0: zero scratch + convert x to bf16 ----------------
__global__ void zero_kernel() {
    int i = blockIdx.x * blockDim.x + threadIdx.x;
    if (i < NN) { g_deg[i] = 0; g_fill[i] = 0; }
    if (i < GG * HH) g_sums[i] = 0.f;
    if (i < GG) g_cnt[i] = 0.f;
}

__global__ void x2bf_kernel(const float* __restrict__ x) {
    int i = blockIdx.x * blockDim.x + threadIdx.x;   // one per 4 floats
    if (i < NN * 32) {
        float4 v = ((const float4*)x)[i];
        uint2 o;
        o.x = f2bf2(v.x, v.y);
        o.y = f2bf2(v.z, v.w);
        g_xbf[i] = o;
    }
}

// ---------------- K1: count in-degrees ----------------
__global__ void deg_kernel(const void* __restrict__ ei) {
    int e = blockIdx.x * blockDim.x + threadIdx.x;
    if (e < EE) {
        int is64 = g_is64;
        int dst = load_idx(ei, (long long)EE + e, is64);
        dst = min(max(dst, 0), NN - 1);      // clamp: never crash
        atomicAdd(&g_deg[dst], 1);
    }
}

// ---------------- K2a/b/c: parallel scan ----------------
__global__ void __launch_bounds__(SCAN_T) scan1_kernel() {
    __shared__ int sh[SCAN_T];
    int b = blockIdx.x, t = threadIdx.x;
    int i = b * SCAN_T + t;
    int v = (i < NN) ? g_deg[i] : 0;
    if (i < NN) g_dinv[i] = rsqrtf((float)(v + 1));
    sh[t] = v;
    __syncthreads();
    #pragma unroll
    for (int s = 1; s < SCAN_T; s <<= 1) {
        int u = (t >= s) ? sh[t - s] : 0;
        __syncthreads();
        sh[t] += u;
        __syncthreads();
    }
    if (i < NN) g_scan[i] = sh[t];
    if (t == SCAN_T - 1) g_bsum[b] = sh[t];
}

__global__ void __launch_bounds__(SCAN_T) scan2_kernel() {
    __shared__ int sh[SCAN_T];
    int t = threadIdx.x;
    sh[t] = (t < SCAN_NB) ? g_bsum[t] : 0;
    __syncthreads();
    #pragma unroll
    for (int s = 1; s < SCAN_T; s <<= 1) {
        int u = (t >= s) ? sh[t - s] : 0;
        __syncthreads();
        sh[t] += u;
        __syncthreads();
    }
    if (t < SCAN_NB) g_bbase[t] = sh[t] - g_bsum[t];
}

__global__ void __launch_bounds__(SCAN_T) scan3_kernel() {
    int b = blockIdx.x, t = threadIdx.x;
    int i = b * SCAN_T + t;
    if (i < NN) g_off[i] = g_bbase[b] + g_scan[i] - g_deg[i];
}

// ---------------- K3: scatter edges into dst-grouped CSR ----------------
__global__ void fill_kernel(const void* __restrict__ ei) {
    int e = blockIdx.x * blockDim.x + threadIdx.x;
    if (e < EE) {
        int is64 = g_is64;
        int src = load_idx(ei, e, is64);
        int dst = load_idx(ei, (long long)EE + e, is64);
        src = min(max(src, 0), NN - 1);
        dst = min(max(dst, 0), NN - 1);
        int pos = g_off[dst] + atomicAdd(&g_fill[dst], 1);
        g_csr[pos] = make_int2(src, __float_as_int(g_dinv[src]));
    }
}

// ---------------- agg helper: one warp aggregates one dst row (bf16 in) -------
__device__ __forceinline__ void fma4(float4& a, float w, const float4& v) {
    a.x = fmaf(w, v.x, a.x); a.y = fmaf(w, v.y, a.y);
    a.z = fmaf(w, v.z, a.z); a.w = fmaf(w, v.w, a.w);
}

__device__ __forceinline__ float4 agg_row_bf(const uint2* __restrict__ sf, int dst, int lane) {
    float di = g_dinv[dst];
    float4 a0 = bf2f4(sf[dst * 32 + lane]);      // self loop
    a0.x *= di; a0.y *= di; a0.z *= di; a0.w *= di;
    float4 a1 = make_float4(0.f, 0.f, 0.f, 0.f);
    float4 a2 = make_float4(0.f, 0.f, 0.f, 0.f);
    float4 a3 = make_float4(0.f, 0.f, 0.f, 0.f);
    int e = g_off[dst];
    int end = e + g_deg[dst];
    // 8-way MLP: 8 independent row loads in flight
    for (; e + 7 < end; e += 8) {
        int2 c0 = g_csr[e + 0];
        int2 c1 = g_csr[e + 1];
        int2 c2 = g_csr[e + 2];
        int2 c3 = g_csr[e + 3];
        int2 c4 = g_csr[e + 4];
        int2 c5 = g_csr[e + 5];
        int2 c6 = g_csr[e + 6];
        int2 c7 = g_csr[e + 7];
        uint2 v0 = sf[c0.x * 32 + lane];
        uint2 v1 = sf[c1.x * 32 + lane];
        uint2 v2 = sf[c2.x * 32 + lane];
        uint2 v3 = sf[c3.x * 32 + lane];
        uint2 v4 = sf[c4.x * 32 + lane];
        uint2 v5 = sf[c5.x * 32 + lane];
        uint2 v6 = sf[c6.x * 32 + lane];
        uint2 v7 = sf[c7.x * 32 + lane];
        fma4(a0, __int_as_float(c0.y), bf2f4(v0));
        fma4(a1, __int_as_float(c1.y), bf2f4(v1));
        fma4(a2, __int_as_float(c2.y), bf2f4(v2));
        fma4(a3, __int_as_float(c3.y), bf2f4(v3));
        fma4(a0, __int_as_float(c4.y), bf2f4(v4));
        fma4(a1, __int_as_float(c5.y), bf2f4(v5));
        fma4(a2, __int_as_float(c6.y), bf2f4(v6));
        fma4(a3, __int_as_float(c7.y), bf2f4(v7));
    }
    for (; e < end; e++) {
        int2 cn = g_csr[e];
        fma4(a0, __int_as_float(cn.y), bf2f4(sf[cn.x * 32 + lane]));
    }
    a0.x += a1.x + a2.x + a3.x;
    a0.y += a1.y + a2.y + a3.y;
    a0.z += a1.z + a2.z + a3.z;
    a0.w += a1.w + a2.w + a3.w;
    a0.x *= di; a0.y *= di; a0.z *= di; a0.w *= di;
    return a0;
}

// ---------------- K4: FUSED  h = relu(Agg(x) @ W1 + b1), h stored bf16 --------
#define GM_BK 16
__global__ void __launch_bounds__(256, 2) fused_agg_gemm(const float* __restrict__ B,
                                                         const float* __restrict__ bias) {
    extern __shared__ float smf[];
    float* As = smf;                 // 128 x 128 row-major (64KB)
    float* Bs = smf + 128 * 128;     // GM_BK x 128        (8KB)
    int tid = threadIdx.x;
    int wid = tid >> 5, lane = tid & 31;
    int row0 = blockIdx.x * 128;
    const uint2* sf = (const uint2*)g_xbf;

    // ---- phase 1: aggregate this block's 128 rows into As ----
    #pragma unroll 1
    for (int r = 0; r < 16; r++) {
        int m = wid * 16 + r;
        int dst = row0 + m;
        float4 a0 = make_float4(0.f, 0.f, 0.f, 0.f);
        if (dst < NN) a0 = agg_row_bf(sf, dst, lane);
        *(float4*)(As + m * 128 + lane * 4) = a0;
    }
    __syncthreads();

    // ---- phase 2: GEMM with packed f32x2: C[m][n] = sum_k As[m][k]*B[k][n] ----
    int tx = tid & 15;   // col group (8 cols = 4 pairs)
    int ty = tid >> 4;   // row group (8 rows)
    u64 acc2[8][4];
    #pragma unroll
    for (int i = 0; i < 8; i++)
        #pragma unroll
        for (int j = 0; j < 4; j++) acc2[i][j] = 0ull;

    for (int k0 = 0; k0 < 128; k0 += GM_BK) {
        #pragma unroll
        for (int l = 0; l < 2; l++) {
            int idx = tid + l * 256;
            int k = idx >> 5;
            int n = (idx & 31) * 4;
            *(float4*)(Bs + k * 128 + n) = *(const float4*)(B + (size_t)(k0 + k) * 128 + n);
        }
        __syncthreads();
        #pragma unroll
        for (int k = 0; k < GM_BK; k++) {
            u64 ap[8];
            #pragma unroll
            for (int i = 0; i < 8; i++)
                ap[i] = pack2_dup(As[(ty * 8 + i) * 128 + k0 + k]);
            const u64* bsp = (const u64*)(Bs + k * 128 + tx * 8);
            u64 bp0 = bsp[0], bp1 = bsp[1], bp2 = bsp[2], bp3 = bsp[3];
            #pragma unroll
            for (int i = 0; i < 8; i++) {
                ffma2(acc2[i][0], ap[i], bp0);
                ffma2(acc2[i][1], ap[i], bp1);
                ffma2(acc2[i][2], ap[i], bp2);
                ffma2(acc2[i][3], ap[i], bp3);
            }
        }
        __syncthreads();
    }

    float bv[8];
    *(float4*)(bv)     = *(const float4*)(bias + tx * 8);
    *(float4*)(bv + 4) = *(const float4*)(bias + tx * 8 + 4);
    #pragma unroll
    for (int i = 0; i < 8; i++) {
        int r = row0 + ty * 8 + i;
        if (r < NN) {
            float o[8];
            #pragma unroll
            for (int j = 0; j < 4; j++) {
                float lo, hi;
                unpack2(lo, hi, acc2[i][j]);
                o[j * 2 + 0] = fmaxf(lo + bv[j * 2 + 0], 0.f);
                o[j * 2 + 1] = fmaxf(hi + bv[j * 2 + 1], 0.f);
            }
            uint4 pk;
            pk.x = f2bf2(o[0], o[1]);
            pk.y = f2bf2(o[2], o[3]);
            pk.z = f2bf2(o[4], o[5]);
            pk.w = f2bf2(o[6], o[7]);
            // 8 bf16 = 16 bytes = 2 uint2 elements -> uint2 index is tx*2
            *(uint4*)(g_hbf + (size_t)r * 32 + tx * 2) = pk;
        }
    }
}

// ---------------- K5: FUSED  Agg(h) + per-graph pool  --------------------------
__global__ void __launch_bounds__(256) agg_pool_kernel(const void* __restrict__ batch) {
    __shared__ float rows[8][128];
    __shared__ int rowg[8];
    int tid = threadIdx.x;
    int wid = tid >> 5, lane = tid & 31;
    int dst = blockIdx.x * 8 + wid;
    int is64 = g_is64;
    const uint2* sf = (const uint2*)g_hbf;

    if (dst < NN) {
        float4 a0 = agg_row_bf(sf, dst, lane);
        *(float4*)(&rows[wid][lane * 4]) = a0;
        if (lane == 0) rowg[wid] = load_idx(batch, dst, is64) & (GG - 1);
    } else if (lane == 0) {
        rowg[wid] = -1;
    }
    __syncthreads();

    if (tid < 128) {
        int t = tid;
        int cur = rowg[0];
        float acc = 0.f;
        #pragma unroll
        for (int r = 0; r < 8; r++) {
            int g = rowg[r];
            if (g < 0) break;
            if (g != cur) {
                atomicAdd(&g_sums[cur * HH + t], acc);
                acc = 0.f; cur = g;
            }
            acc += rows[r][t];
        }
        if (cur >= 0) atomicAdd(&g_sums[cur * HH + t], acc);
    } else if (tid == 128) {
        int cur = rowg[0];
        float c = 0.f;
        #pragma unroll
        for (int r = 0; r < 8; r++) {
            int g = rowg[r];
            if (g < 0) break;
            if (g != cur) { atomicAdd(&g_cnt[cur], c); c = 0.f; cur = g; }
            c += 1.f;
        }
        if (cur >= 0) atomicAdd(&g_cnt[cur], c);
    }
}

// ---------------- K7a: fold head weights ----------------
__global__ void combine_kernel(const float* __restrict__ W2, const float* __restrict__ b2,
                               const float* __restrict__ Wlin, const float* __restrict__ blin) {
    __shared__ float wl[HH];
    int c = blockIdx.x;
    int k = threadIdx.x;           // 0..127
    wl[k] = Wlin[k * CC + c];
    __syncthreads();
    float s = 0.f;
    #pragma unroll 8
    for (int j = 0; j < HH; j++) s = fmaf(W2[k * HH + j], wl[j], s);
    g_Wc[k * CC + c] = s;
    if (k == 0) {
        float sb = blin[c];
        for (int j = 0; j < HH; j++) sb = fmaf(b2[j], wl[j], sb);
        g_bc[c] = sb;
    }
}

// ---------------- K7b: logits = (sums/cnt) @ Wc + bc ----------------
__global__ void final_kernel(float* __restrict__ out) {
    int g = blockIdx.x;            // 0..63
    int warp = threadIdx.x >> 5;   // 0..9 (one warp per class)
    int lane = threadIdx.x & 31;
    float inv = 1.f / fmaxf(g_cnt[g], 1.f);
    if (warp < CC) {
        float s = 0.f;
        for (int k = lane; k < HH; k += 32)
            s = fmaf(g_sums[g * HH + k] * inv, g_Wc[k * CC + warp], s);
        #pragma unroll
        for (int o = 16; o > 0; o >>= 1) s += __shfl_down_sync(0xffffffffu, s, o);
        if (lane == 0) out[g * CC + warp] = s + g_bc[warp];
    }
}

// ---------------- host launch ----------------
extern "C" void kernel_launch(void* const* d_in, const int* in_sizes, int n_in,
                              void* d_out, int out_size) {
    const float* x    = (const float*)d_in[0];
    const float* W1   = (const float*)d_in[1];
    const float* b1   = (const float*)d_in[2];
    const float* W2   = (const float*)d_in[3];
    const float* b2   = (const float*)d_in[4];
    const float* Wlin = (const float*)d_in[5];
    const float* blin = (const float*)d_in[6];
    const void*  ei   = d_in[7];   // edge_index: int32 or int64, detected on device
    const void*  bt   = d_in[8];   // batch: same index dtype
    float* out = (float*)d_out;

    const int FUSED_SMEM = (128 * 128 + GM_BK * 128) * (int)sizeof(float);  // 72KB
    cudaFuncSetAttribute(fused_agg_gemm, cudaFuncAttributeMaxDynamicSharedMemorySize, FUSED_SMEM);

    detect_kernel<<<1, 256>>>(ei);
    zero_kernel<<<(NN + 255) / 256, 256>>>();
    x2bf_kernel<<<(NN * 32 + 255) / 256, 256>>>(x);
    deg_kernel<<<(EE + 255) / 256, 256>>>(ei);
    scan1_kernel<<<SCAN_NB, SCAN_T>>>();
    scan2_kernel<<<1, SCAN_T>>>();
    scan3_kernel<<<SCAN_NB, SCAN_T>>>();
    fill_kernel<<<(EE + 255) / 256, 256>>>(ei);

    // layer 1 fused: h = relu(Agg(x) @ W1 + b1)  (reads g_xbf, writes g_hbf bf16)
    fused_agg_gemm<<<(NN + 127) / 128, 256, FUSED_SMEM>>>(W1, b1);

    // layer 2 folded + fused: pool(Agg(h)); head on 64x128
    agg_pool_kernel<<<(NN + 7) / 8, 256>>>(bt);
    combine_kernel<<<CC, 128>>>(W2, b2, Wlin, blin);
    final_kernel<<<GG, 320>>>(out);
}

// round 11
// speedup vs baseline: 2.4609x; 1.1469x over previous
#include <cuda_runtime.h>
#include <cuda_bf16.h>

// Problem constants (match reference)
#define NN 50000
#define EE 600000
#define GG 64
#define HH 128
#define CC 10

#define SCAN_T 256
#define SCAN_NB ((NN + SCAN_T - 1) / SCAN_T)   // 196

typedef unsigned long long u64;
typedef unsigned int u32;

// ---------------- scratch (static device globals; no runtime alloc) ----------------
__device__ int   g_is64;           // 1 if index tensors are int64, 0 if int32
__device__ int   g_deg[NN];        // in-degree (without self loop)
__device__ int   g_off[NN];        // CSR exclusive offsets
__device__ int   g_fill[NN];       // CSR fill cursors
__device__ float g_dinv[NN];       // rsqrt(deg+1)
__device__ int   g_scan[NN];       // block-local inclusive scan of deg
__device__ int   g_bsum[SCAN_NB];  // per-block degree totals
__device__ int   g_bbase[SCAN_NB]; // exclusive scan of block totals
__device__ int2  g_csr[EE];        // {src, bits(dinv[src])} grouped by dst
__device__ uint4 g_xbf[NN * 16];   // x in bf16 (row = 16 uint4 = 128 bf16)
__device__ uint4 g_hbf[NN * 16];   // h = relu(Agg(x)@W1+b1) in bf16
__device__ float g_sums[GG * HH];  // per-graph feature sums
__device__ float g_cnt[GG];        // per-graph node counts

// ---------------- packed f32x2 helpers ----------------
__device__ __forceinline__ u64 pack2_dup(float v) {
    u64 r; asm("mov.b64 %0, {%1, %1};" : "=l"(r) : "f"(v)); return r;
}
__device__ __forceinline__ void ffma2(u64& d, u64 a, u64 b) {
    asm("fma.rn.f32x2 %0, %1, %2, %0;" : "+l"(d) : "l"(a), "l"(b));
}
__device__ __forceinline__ void unpack2(float& lo, float& hi, u64 v) {
    asm("mov.b64 {%0, %1}, %2;" : "=f"(lo), "=f"(hi) : "l"(v));
}

// ---------------- bf16 helpers ----------------
__device__ __forceinline__ float4 bf2f4(u32 a, u32 b) {
    __nv_bfloat162 p0 = *(__nv_bfloat162*)&a;
    __nv_bfloat162 p1 = *(__nv_bfloat162*)&b;
    float2 f0 = __bfloat1622float2(p0);
    float2 f1 = __bfloat1622float2(p1);
    return make_float4(f0.x, f0.y, f1.x, f1.y);
}
__device__ __forceinline__ u32 f2bf2(float a, float b) {
    __nv_bfloat162 p = __float22bfloat162_rn(make_float2(a, b));
    return *(u32*)&p;
}

// ---------------- index load helper (dtype-agnostic) ----------------
__device__ __forceinline__ int load_idx(const void* p, long long i, int is64) {
    if (is64) return (int)(((const long long*)p)[i]);
    return ((const int*)p)[i];
}

// ---------------- K0: zero scratch + dtype detect (block 0) ----------------
__global__ void zero_kernel(const void* ei) {
    int i = blockIdx.x * blockDim.x + threadIdx.x;
    if (i < NN) { g_deg[i] = 0; g_fill[i] = 0; }
    if (i < GG * HH) g_sums[i] = 0.f;
    if (i < GG) g_cnt[i] = 0.f;
    if (blockIdx.x == 0) {
        __shared__ int bad;
        if (threadIdx.x == 0) bad = 0;
        __syncthreads();
        const long long* p = (const long long*)ei;
        for (int k = threadIdx.x; k < 1024; k += blockDim.x) {
            long long v = p[k];
            if (v < 0 || v >= (long long)NN) bad = 1;
        }
        __syncthreads();
        if (threadIdx.x == 0) g_is64 = bad ? 0 : 1;
    }
}

// ---------------- K1: convert x->bf16  AND  count in-degrees ----------------
__global__ void prep_kernel(const float* __restrict__ x, const void* __restrict__ ei) {
    int i = blockIdx.x * blockDim.x + threadIdx.x;
    if (i < NN * 16) {
        float4 va = ((const float4*)x)[i * 2];
        float4 vb = ((const float4*)x)[i * 2 + 1];
        uint4 o;
        o.x = f2bf2(va.x, va.y);
        o.y = f2bf2(va.z, va.w);
        o.z = f2bf2(vb.x, vb.y);
        o.w = f2bf2(vb.z, vb.w);
        g_xbf[i] = o;
    }
    if (i < EE) {
        int is64 = g_is64;
        int dst = load_idx(ei, (long long)EE + i, is64);
        dst = min(max(dst, 0), NN - 1);
        atomicAdd(&g_deg[dst], 1);
    }
}

// ---------------- K2a/b/c: parallel scan ----------------
__global__ void __launch_bounds__(SCAN_T) scan1_kernel() {
    __shared__ int sh[SCAN_T];
    int b = blockIdx.x, t = threadIdx.x;
    int i = b * SCAN_T + t;
    int v = (i < NN) ? g_deg[i] : 0;
    if (i < NN) g_dinv[i] = rsqrtf((float)(v + 1));
    sh[t] = v;
    __syncthreads();
    #pragma unroll
    for (int s = 1; s < SCAN_T; s <<= 1) {
        int u = (t >= s) ? sh[t - s] : 0;
        __syncthreads();
        sh[t] += u;
        __syncthreads();
    }
    if (i < NN) g_scan[i] = sh[t];
    if (t == SCAN_T - 1) g_bsum[b] = sh[t];
}

__global__ void __launch_bounds__(SCAN_T) scan2_kernel() {
    __shared__ int sh[SCAN_T];
    int t = threadIdx.x;
    sh[t] = (t < SCAN_NB) ? g_bsum[t] : 0;
    __syncthreads();
    #pragma unroll
    for (int s = 1; s < SCAN_T; s <<= 1) {
        int u = (t >= s) ? sh[t - s] : 0;
        __syncthreads();
        sh[t] += u;
        __syncthreads();
    }
    if (t < SCAN_NB) g_bbase[t] = sh[t] - g_bsum[t];
}

__global__ void __launch_bounds__(SCAN_T) scan3_kernel() {
    int b = blockIdx.x, t = threadIdx.x;
    int i = b * SCAN_T + t;
    if (i < NN) g_off[i] = g_bbase[b] + g_scan[i] - g_deg[i];
}

// ---------------- K3: scatter edges into dst-grouped CSR ----------------
__global__ void fill_kernel(const void* __restrict__ ei) {
    int e = blockIdx.x * blockDim.x + threadIdx.x;
    if (e < EE) {
        int is64 = g_is64;
        int src = load_idx(ei, e, is64);
        int dst = load_idx(ei, (long long)EE + e, is64);
        src = min(max(src, 0), NN - 1);
        dst = min(max(dst, 0), NN - 1);
        int pos = g_off[dst] + atomicAdd(&g_fill[dst], 1);
        g_csr[pos] = make_int2(src, __float_as_int(g_dinv[src]));
    }
}

// ---------------- dual-row agg: each lane covers 16B (8 bf16) of ONE row ------
// lane = half*16 + sub : half selects which of the warp's 2 rows, sub the 16B chunk.
// Predicated batch-4: constant 4-deep MLP, no serial tail.
__device__ __forceinline__ void fma4(float4& a, float w, const float4& v) {
    a.x = fmaf(w, v.x, a.x); a.y = fmaf(w, v.y, a.y);
    a.z = fmaf(w, v.z, a.z); a.w = fmaf(w, v.w, a.w);
}

__device__ __forceinline__ void agg_row2_bf(const uint4* __restrict__ sf, int dst, int sub,
                                            float4& o0, float4& o1) {
    float di = g_dinv[dst];
    uint4 sv = sf[dst * 16 + sub];                 // self loop
    float4 a0 = bf2f4(sv.x, sv.y);
    float4 a1 = bf2f4(sv.z, sv.w);
    a0.x *= di; a0.y *= di; a0.z *= di; a0.w *= di;
    a1.x *= di; a1.y *= di; a1.z *= di; a1.w *= di;
    float4 b0 = make_float4(0.f, 0.f, 0.f, 0.f);
    float4 b1 = make_float4(0.f, 0.f, 0.f, 0.f);

    int e0 = g_off[dst];
    int end = e0 + g_deg[dst];
    int last = end - 1;
    for (int b = e0; b < end; b += 4) {
        int i1 = b + 1, i2 = b + 2, i3 = b + 3;
        int2 c0 = g_csr[b];
        int2 c1 = g_csr[min(i1, last)];
        int2 c2 = g_csr[min(i2, last)];
        int2 c3 = g_csr[min(i3, last)];
        uint4 v0 = sf[c0.x * 16 + sub];
        uint4 v1 = sf[c1.x * 16 + sub];
        uint4 v2 = sf[c2.x * 16 + sub];
        uint4 v3 = sf[c3.x * 16 + sub];
        float w0 = __int_as_float(c0.y);
        float w1 = (i1 < end) ? __int_as_float(c1.y) : 0.f;
        float w2 = (i2 < end) ? __int_as_float(c2.y) : 0.f;
        float w3 = (i3 < end) ? __int_as_float(c3.y) : 0.f;
        fma4(a0, w0, bf2f4(v0.x, v0.y)); fma4(a1, w0, bf2f4(v0.z, v0.w));
        fma4(b0, w1, bf2f4(v1.x, v1.y)); fma4(b1, w1, bf2f4(v1.z, v1.w));
        fma4(a0, w2, bf2f4(v2.x, v2.y)); fma4(a1, w2, bf2f4(v2.z, v2.w));
        fma4(b0, w3, bf2f4(v3.x, v3.y)); fma4(b1, w3, bf2f4(v3.z, v3.w));
    }
    a0.x += b0.x; a0.y += b0.y; a0.z += b0.z; a0.w += b0.w;
    a1.x += b1.x; a1.y += b1.y; a1.z += b1.z; a1.w += b1.w;
    a0.x *= di; a0.y *= di; a0.z *= di; a0.w *= di;
    a1.x *= di; a1.y *= di; a1.z *= di; a1.w *= di;
    o0 = a0; o1 = a1;
}

// ---------------- K4: FUSED  h = relu(Agg(x) @ W1 + b1), h stored bf16 --------
#define GM_BK 16
__global__ void __launch_bounds__(256, 2) fused_agg_gemm(const float* __restrict__ B,
                                                         const float* __restrict__ bias) {
    extern __shared__ float smf[];
    float* As = smf;                 // 128 x 128 row-major (64KB)
    float* Bs = smf + 128 * 128;     // GM_BK x 128        (8KB)
    int tid = threadIdx.x;
    int wid = tid >> 5, lane = tid & 31;
    int sub = lane & 15, half = lane >> 4;
    int row0 = blockIdx.x * 128;
    const uint4* sfx = (const uint4*)g_xbf;

    // ---- phase 1: aggregate this block's 128 rows (2 rows per warp-iter) ----
    #pragma unroll 1
    for (int r = 0; r < 8; r++) {
        int m = wid * 16 + r * 2 + half;
        int dst = row0 + m;
        float4 o0 = make_float4(0.f, 0.f, 0.f, 0.f);
        float4 o1 = make_float4(0.f, 0.f, 0.f, 0.f);
        if (dst < NN) agg_row2_bf(sfx, dst, sub, o0, o1);
        *(float4*)(As + m * 128 + sub * 8)     = o0;
        *(float4*)(As + m * 128 + sub * 8 + 4) = o1;
    }
    __syncthreads();

    // ---- phase 2: GEMM with packed f32x2: C[m][n] = sum_k As[m][k]*B[k][n] ----
    int tx = tid & 15;   // col group (8 cols = 4 pairs)
    int ty = tid >> 4;   // row group (8 rows)
    u64 acc2[8][4];
    #pragma unroll
    for (int i = 0; i < 8; i++)
        #pragma unroll
        for (int j = 0; j < 4; j++) acc2[i][j] = 0ull;

    for (int k0 = 0; k0 < 128; k0 += GM_BK) {
        #pragma unroll
        for (int l = 0; l < 2; l++) {
            int idx = tid + l * 256;
            int k = idx >> 5;
            int n = (idx & 31) * 4;
            *(float4*)(Bs + k * 128 + n) = *(const float4*)(B + (size_t)(k0 + k) * 128 + n);
        }
        __syncthreads();
        #pragma unroll
        for (int k = 0; k < GM_BK; k++) {
            u64 ap[8];
            #pragma unroll
            for (int i = 0; i < 8; i++)
                ap[i] = pack2_dup(As[(ty * 8 + i) * 128 + k0 + k]);
            const u64* bsp = (const u64*)(Bs + k * 128 + tx * 8);
            u64 bp0 = bsp[0], bp1 = bsp[1], bp2 = bsp[2], bp3 = bsp[3];
            #pragma unroll
            for (int i = 0; i < 8; i++) {
                ffma2(acc2[i][0], ap[i], bp0);
                ffma2(acc2[i][1], ap[i], bp1);
                ffma2(acc2[i][2], ap[i], bp2);
                ffma2(acc2[i][3], ap[i], bp3);
            }
        }
        __syncthreads();
    }

    float bv[8];
    *(float4*)(bv)     = *(const float4*)(bias + tx * 8);
    *(float4*)(bv + 4) = *(const float4*)(bias + tx * 8 + 4);
    #pragma unroll
    for (int i = 0; i < 8; i++) {
        int r = row0 + ty * 8 + i;
        if (r < NN) {
            float o[8];
            #pragma unroll
            for (int j = 0; j < 4; j++) {
                float lo, hi;
                unpack2(lo, hi, acc2[i][j]);
                o[j * 2 + 0] = fmaxf(lo + bv[j * 2 + 0], 0.f);
                o[j * 2 + 1] = fmaxf(hi + bv[j * 2 + 1], 0.f);
            }
            uint4 pk;
            pk.x = f2bf2(o[0], o[1]);
            pk.y = f2bf2(o[2], o[3]);
            pk.z = f2bf2(o[4], o[5]);
            pk.w = f2bf2(o[6], o[7]);
            g_hbf[(size_t)r * 16 + tx] = pk;   // 8 bf16 = 16B = one uint4
        }
    }
}

// ---------------- K5: FUSED  Agg(h) + per-graph pool (16 rows / block) --------
__global__ void __launch_bounds__(256) agg_pool_kernel(const void* __restrict__ batch) {
    __shared__ float rows[16][128];
    __shared__ int rowg[16];
    int tid = threadIdx.x;
    int wid = tid >> 5, lane = tid & 31;
    int sub = lane & 15, half = lane >> 4;
    int r = wid * 2 + half;                // 0..15
    int dst = blockIdx.x * 16 + r;
    int is64 = g_is64;
    const uint4* sfh = (const uint4*)g_hbf;

    if (dst < NN) {
        float4 o0, o1;
        agg_row2_bf(sfh, dst, sub, o0, o1);
        *(float4*)(&rows[r][sub * 8])     = o0;
        *(float4*)(&rows[r][sub * 8 + 4]) = o1;
        if (sub == 0) rowg[r] = load_idx(batch, dst, is64) & (GG - 1);
    } else if (sub == 0) {
        rowg[r] = -1;
    }
    __syncthreads();

    if (tid < 128) {
        int t = tid;
        int cur = rowg[0];
        float acc = 0.f;
        #pragma unroll
        for (int rr = 0; rr < 16; rr++) {
            int g = rowg[rr];
            if (g < 0) break;
            if (g != cur) {
                atomicAdd(&g_sums[cur * HH + t], acc);
                acc = 0.f; cur = g;
            }
            acc += rows[rr][t];
        }
        if (cur >= 0) atomicAdd(&g_sums[cur * HH + t], acc);
    } else if (tid == 128) {
        int cur = rowg[0];
        float c = 0.f;
        #pragma unroll
        for (int rr = 0; rr < 16; rr++) {
            int g = rowg[rr];
            if (g < 0) break;
            if (g != cur) { atomicAdd(&g_cnt[cur], c); c = 0.f; cur = g; }
            c += 1.f;
        }
        if (cur >= 0) atomicAdd(&g_cnt[cur], c);
    }
}

// ---------------- K6: per-graph head: z = p@W2+b2 ; logits = z@Wlin+blin ------
__global__ void __launch_bounds__(128) final_kernel(const float* __restrict__ W2,
                                                    const float* __restrict__ b2,
                                                    const float* __restrict__ Wlin,
                                                    const float* __restrict__ blin,
                                                    float* __restrict__ out) {
    __shared__ float p[HH];
    __shared__ float z[HH];
    int g = blockIdx.x;            // 0..63
    int t = threadIdx.x;           // 0..127
    float inv = 1.f / fmaxf(g_cnt[g], 1.f);
    p[t] = g_sums[g * HH + t] * inv;
    __syncthreads();
    float s = b2[t];
    #pragma unroll 8
    for (int k = 0; k < HH; k++) s = fmaf(p[k], W2[k * HH + t], s);
    z[t] = s;
    __syncthreads();
    if (t < CC) {
        float l = blin[t];
        #pragma unroll 8
        for (int j = 0; j < HH; j++) l = fmaf(z[j], Wlin[j * CC + t], l);
        out[g * CC + t] = l;
    }
}

// ---------------- host launch ----------------
extern "C" void kernel_launch(void* const* d_in, const int* in_sizes, int n_in,
                              void* d_out, int out_size) {
    const float* x    = (const float*)d_in[0];
    const float* W1   = (const float*)d_in[1];
    const float* b1   = (const float*)d_in[2];
    const float* W2   = (const float*)d_in[3];
    const float* b2   = (const float*)d_in[4];
    const float* Wlin = (const float*)d_in[5];
    const float* blin = (const float*)d_in[6];
    const void*  ei   = d_in[7];   // edge_index: int32 or int64, detected on device
    const void*  bt   = d_in[8];   // batch: same index dtype
    float* out = (float*)d_out;

    const int FUSED_SMEM = (128 * 128 + GM_BK * 128) * (int)sizeof(float);  // 72KB
    cudaFuncSetAttribute(fused_agg_gemm, cudaFuncAttributeMaxDynamicSharedMemorySize, FUSED_SMEM);

    zero_kernel<<<(NN + 255) / 256, 256>>>(ei);                 // + dtype detect
    prep_kernel<<<(NN * 16 + 255) / 256, 256>>>(x, ei);         // x->bf16 + degrees
    scan1_kernel<<<SCAN_NB, SCAN_T>>>();
    scan2_kernel<<<1, SCAN_T>>>();
    scan3_kernel<<<SCAN_NB, SCAN_T>>>();
    fill_kernel<<<(EE + 255) / 256, 256>>>(ei);

    // layer 1 fused: h = relu(Agg(x) @ W1 + b1)  (reads g_xbf, writes g_hbf bf16)
    fused_agg_gemm<<<(NN + 127) / 128, 256, FUSED_SMEM>>>(W1, b1);

    // layer 2 folded + fused: pool(Agg(h)); then per-graph head
    agg_pool_kernel<<<(NN + 15) / 16, 256>>>(bt);
    final_kernel<<<GG, 128>>>(W2, b2, Wlin, blin, out);
}

// round 14
// speedup vs baseline: 2.9074x; 1.1814x over previous
#include <cuda_runtime.h>
#include <cuda_bf16.h>
#include <cstdint>

// Problem constants (match reference)
#define NN 50000
#define EE 600000
#define GG 64
#define HH 128
#define CC 10

#define SCAN_T 256
#define SCAN_NB ((NN + SCAN_T - 1) / SCAN_T)   // 196

typedef unsigned long long u64;
typedef unsigned int u32;
typedef unsigned short u16;

// ---------------- scratch (static device globals; no runtime alloc) ----------------
__device__ int   g_is64;           // 1 if index tensors are int64, 0 if int32
__device__ int   g_deg[NN];        // in-degree (without self loop)
__device__ int   g_off[NN];        // CSR exclusive offsets
__device__ int   g_fill[NN];       // CSR fill cursors
__device__ float g_dinv[NN];       // rsqrt(deg+1)
__device__ int   g_scan[NN];       // block-local inclusive scan of deg
__device__ int   g_bsum[SCAN_NB];  // per-block degree totals
__device__ int2  g_csr[EE];        // {src, bits(dinv[src])} grouped by dst
__device__ uint4 g_xbf[NN * 16];   // x in bf16 (row = 16 uint4 = 128 bf16)
__device__ uint4 g_hbf[NN * 16];   // h = relu(Agg(x)@W1+b1) in bf16
__device__ float g_sums[GG * HH];  // per-graph feature sums
__device__ float g_cnt[GG];        // per-graph node counts

// ---------------- bf16 helpers ----------------
__device__ __forceinline__ float4 bf2f4(u32 a, u32 b) {
    __nv_bfloat162 p0 = *(__nv_bfloat162*)&a;
    __nv_bfloat162 p1 = *(__nv_bfloat162*)&b;
    float2 f0 = __bfloat1622float2(p0);
    float2 f1 = __bfloat1622float2(p1);
    return make_float4(f0.x, f0.y, f1.x, f1.y);
}
__device__ __forceinline__ u32 f2bf2(float a, float b) {
    __nv_bfloat162 p = __float22bfloat162_rn(make_float2(a, b));
    return *(u32*)&p;
}

// ---------------- warp-level bf16 MMA (sm_80+ PTX, legal on compute_103) -------
__device__ __forceinline__ void mma16816(float* d, u32 a0, u32 a1, u32 a2, u32 a3,
                                         u32 b0, u32 b1) {
    asm volatile(
        "mma.sync.aligned.m16n8k16.row.col.f32.bf16.bf16.f32 "
        "{%0,%1,%2,%3}, {%4,%5,%6,%7}, {%8,%9}, {%0,%1,%2,%3};"
        : "+f"(d[0]), "+f"(d[1]), "+f"(d[2]), "+f"(d[3])
        : "r"(a0), "r"(a1), "r"(a2), "r"(a3), "r"(b0), "r"(b1));
}

// ---------------- index load helper (dtype-agnostic) ----------------
__device__ __forceinline__ int load_idx(const void* p, long long i, int is64) {
    if (is64) return (int)(((const long long*)p)[i]);
    return ((const int*)p)[i];
}

// ---------------- K0: zero scratch + dtype detect (block 0) ----------------
__global__ void zero_kernel(const void* ei) {
    int i = blockIdx.x * blockDim.x + threadIdx.x;
    if (i < NN) { g_deg[i] = 0; g_fill[i] = 0; }
    if (i < GG * HH) g_sums[i] = 0.f;
    if (i < GG) g_cnt[i] = 0.f;
    if (blockIdx.x == 0) {
        __shared__ int bad;
        if (threadIdx.x == 0) bad = 0;
        __syncthreads();
        const long long* p = (const long long*)ei;
        for (int k = threadIdx.x; k < 1024; k += blockDim.x) {
            long long v = p[k];
            if (v < 0 || v >= (long long)NN) bad = 1;
        }
        __syncthreads();
        if (threadIdx.x == 0) g_is64 = bad ? 0 : 1;
    }
}

// ---------------- K1: convert x->bf16  AND  count in-degrees ----------------
__global__ void prep_kernel(const float* __restrict__ x, const void* __restrict__ ei) {
    int i = blockIdx.x * blockDim.x + threadIdx.x;
    if (i < NN * 16) {
        float4 va = ((const float4*)x)[i * 2];
        float4 vb = ((const float4*)x)[i * 2 + 1];
        uint4 o;
        o.x = f2bf2(va.x, va.y);
        o.y = f2bf2(va.z, va.w);
        o.z = f2bf2(vb.x, vb.y);
        o.w = f2bf2(vb.z, vb.w);
        g_xbf[i] = o;
    }
    if (i < EE) {
        int is64 = g_is64;
        int dst = load_idx(ei, (long long)EE + i, is64);
        dst = min(max(dst, 0), NN - 1);
        atomicAdd(&g_deg[dst], 1);
    }
}

// ---------------- K2a: per-block inclusive scan of deg + dinv ----------------
__global__ void __launch_bounds__(SCAN_T) scan1_kernel() {
    __shared__ int sh[SCAN_T];
    int b = blockIdx.x, t = threadIdx.x;
    int i = b * SCAN_T + t;
    int v = (i < NN) ? g_deg[i] : 0;
    if (i < NN) g_dinv[i] = rsqrtf((float)(v + 1));
    sh[t] = v;
    __syncthreads();
    #pragma unroll
    for (int s = 1; s < SCAN_T; s <<= 1) {
        int u = (t >= s) ? sh[t - s] : 0;
        __syncthreads();
        sh[t] += u;
        __syncthreads();
    }
    if (i < NN) g_scan[i] = sh[t];
    if (t == SCAN_T - 1) g_bsum[b] = sh[t];
}

// ---------------- K2b: per-block base (inline reduce of block sums) + offsets --
__global__ void __launch_bounds__(SCAN_T) scan3_kernel() {
    __shared__ int red[SCAN_T];
    int b = blockIdx.x, t = threadIdx.x;
    red[t] = (t < b && t < SCAN_NB) ? g_bsum[t] : 0;
    __syncthreads();
    #pragma unroll
    for (int s = SCAN_T / 2; s > 0; s >>= 1) {
        if (t < s) red[t] += red[t + s];
        __syncthreads();
    }
    int base = red[0];
    int i = b * SCAN_T + t;
    if (i < NN) g_off[i] = base + g_scan[i] - g_deg[i];
}

// ---------------- K3: scatter edges into dst-grouped CSR ----------------
__global__ void fill_kernel(const void* __restrict__ ei) {
    int e = blockIdx.x * blockDim.x + threadIdx.x;
    if (e < EE) {
        int is64 = g_is64;
        int src = load_idx(ei, e, is64);
        int dst = load_idx(ei, (long long)EE + e, is64);
        src = min(max(src, 0), NN - 1);
        dst = min(max(dst, 0), NN - 1);
        int pos = g_off[dst] + atomicAdd(&g_fill[dst], 1);
        g_csr[pos] = make_int2(src, __float_as_int(g_dinv[src]));
    }
}

// ---------------- dual-row agg (predicated batch-4, no serial tail) -----------
__device__ __forceinline__ void fma4(float4& a, float w, const float4& v) {
    a.x = fmaf(w, v.x, a.x); a.y = fmaf(w, v.y, a.y);
    a.z = fmaf(w, v.z, a.z); a.w = fmaf(w, v.w, a.w);
}

__device__ __forceinline__ void agg_row2_bf(const uint4* __restrict__ sf, int dst, int sub,
                                            float4& o0, float4& o1) {
    float di = g_dinv[dst];
    uint4 sv = sf[dst * 16 + sub];                 // self loop
    float4 a0 = bf2f4(sv.x, sv.y);
    float4 a1 = bf2f4(sv.z, sv.w);
    a0.x *= di; a0.y *= di; a0.z *= di; a0.w *= di;
    a1.x *= di; a1.y *= di; a1.z *= di; a1.w *= di;
    float4 b0 = make_float4(0.f, 0.f, 0.f, 0.f);
    float4 b1 = make_float4(0.f, 0.f, 0.f, 0.f);

    int e0 = g_off[dst];
    int end = e0 + g_deg[dst];
    int last = end - 1;
    for (int b = e0; b < end; b += 4) {
        int i1 = b + 1, i2 = b + 2, i3 = b + 3;
        int2 c0 = g_csr[b];
        int2 c1 = g_csr[min(i1, last)];
        int2 c2 = g_csr[min(i2, last)];
        int2 c3 = g_csr[min(i3, last)];
        uint4 v0 = sf[c0.x * 16 + sub];
        uint4 v1 = sf[c1.x * 16 + sub];
        uint4 v2 = sf[c2.x * 16 + sub];
        uint4 v3 = sf[c3.x * 16 + sub];
        float w0 = __int_as_float(c0.y);
        float w1 = (i1 < end) ? __int_as_float(c1.y) : 0.f;
        float w2 = (i2 < end) ? __int_as_float(c2.y) : 0.f;
        float w3 = (i3 < end) ? __int_as_float(c3.y) : 0.f;
        fma4(a0, w0, bf2f4(v0.x, v0.y)); fma4(a1, w0, bf2f4(v0.z, v0.w));
        fma4(b0, w1, bf2f4(v1.x, v1.y)); fma4(b1, w1, bf2f4(v1.z, v1.w));
        fma4(a0, w2, bf2f4(v2.x, v2.y)); fma4(a1, w2, bf2f4(v2.z, v2.w));
        fma4(b0, w3, bf2f4(v3.x, v3.y)); fma4(b1, w3, bf2f4(v3.z, v3.w));
    }
    a0.x += b0.x; a0.y += b0.y; a0.z += b0.z; a0.w += b0.w;
    a1.x += b1.x; a1.y += b1.y; a1.z += b1.z; a1.w += b1.w;
    a0.x *= di; a0.y *= di; a0.z *= di; a0.w *= di;
    a1.x *= di; a1.y *= di; a1.z *= di; a1.w *= di;
    o0 = a0; o1 = a1;
}

// ---------------- K4: FUSED  h = relu(Agg(x) @ W1 + b1) via split-bf16 MMA ----
// W1 = Whi + Wlo (two bf16 planes, round-to-nearest): coherent weight error
// drops from 2^-9 to ~2^-17. Two MMAs per tile into the same fp32 accumulators.
// SMEM: [512:1024) bias fp32, [1024,+34816) A bf16 [128][136],
//       [35840,+34816) Bhi [128n][136k], [70656,+34816) Blo. 105472B, 2 CTA/SM.
#define SM_BIAS 512
#define SM_A 1024
#define SM_BHI (1024 + 34816)
#define SM_BLO (1024 + 34816 + 34816)
#define FUSED_SMEM (1024 + 34816 + 34816 + 34816)
#define AST 136   // A/B row stride in bf16
#define ASTW 68   // in 32-bit words

__global__ void __launch_bounds__(256, 2)
fused_agg_mma(const float* __restrict__ W1, const float* __restrict__ b1) {
    extern __shared__ char smc[];
    float* bias_s = (float*)(smc + SM_BIAS);
    u32* Aw  = (u32*)(smc + SM_A);
    u32* BwH = (u32*)(smc + SM_BHI);
    u32* BwL = (u32*)(smc + SM_BLO);
    int tid = threadIdx.x;
    int wid = tid >> 5, lane = tid & 31;
    int sub = lane & 15, half = lane >> 4;
    int row0 = blockIdx.x * 128;

    if (tid < 128) bias_s[tid] = b1[tid];

    // ---- B tiles: Bhi[n][k] = rn(W1[k][n]), Blo[n][k] = rn(W1 - Bhi) ----
    for (int idx = tid; idx < 128 * 128; idx += 256) {
        int k = idx >> 7, n = idx & 127;
        float w = W1[idx];
        __nv_bfloat16 hi = __float2bfloat16_rn(w);
        __nv_bfloat16 lo = __float2bfloat16_rn(w - __bfloat162float(hi));
        ((u16*)(smc + SM_BHI))[n * AST + k] = *(u16*)&hi;
        ((u16*)(smc + SM_BLO))[n * AST + k] = *(u16*)&lo;
    }

    // ---- A tile: aggregate 128 rows into As[m][k] bf16 (stride 136) ----
    const uint4* sfx = (const uint4*)g_xbf;
    #pragma unroll 1
    for (int r = 0; r < 8; r++) {
        int m = wid * 16 + r * 2 + half;
        int dst = row0 + m;
        float4 o0 = make_float4(0.f, 0.f, 0.f, 0.f);
        float4 o1 = make_float4(0.f, 0.f, 0.f, 0.f);
        if (dst < NN) agg_row2_bf(sfx, dst, sub, o0, o1);
        uint4 pk;
        pk.x = f2bf2(o0.x, o0.y); pk.y = f2bf2(o0.z, o0.w);
        pk.z = f2bf2(o1.x, o1.y); pk.w = f2bf2(o1.z, o1.w);
        *(uint4*)(smc + SM_A + m * (AST * 2) + sub * 16) = pk;
    }
    __syncthreads();

    // ---- MMA: each warp computes rows [wid*16, +16) x all 128 cols ----
    int g = lane >> 2, tc = lane & 3;
    int wrow = wid * 16;
    float acc[16][4];
    #pragma unroll
    for (int j = 0; j < 16; j++)
        #pragma unroll
        for (int q = 0; q < 4; q++) acc[j][q] = 0.f;

    #pragma unroll 1
    for (int ks = 0; ks < 8; ks++) {
        int k0w = ks * 8;                       // 16 bf16 = 8 words
        u32 a0 = Aw[(wrow + g) * ASTW + k0w + tc];
        u32 a1 = Aw[(wrow + g + 8) * ASTW + k0w + tc];
        u32 a2 = Aw[(wrow + g) * ASTW + k0w + tc + 4];
        u32 a3 = Aw[(wrow + g + 8) * ASTW + k0w + tc + 4];
        #pragma unroll
        for (int j = 0; j < 16; j++) {
            int bi = (j * 8 + g) * ASTW + k0w + tc;
            u32 bh0 = BwH[bi], bh1 = BwH[bi + 4];
            u32 bl0 = BwL[bi], bl1 = BwL[bi + 4];
            mma16816(acc[j], a0, a1, a2, a3, bh0, bh1);
            mma16816(acc[j], a0, a1, a2, a3, bl0, bl1);
        }
    }
    __syncthreads();     // done reading As/Bs; reuse As for output staging

    // ---- epilogue: bias + relu, pack bf16 into As, then coalesced store ----
    #pragma unroll
    for (int j = 0; j < 16; j++) {
        int c = j * 8 + tc * 2;
        float bv0 = bias_s[c], bv1 = bias_s[c + 1];
        u32 lo = f2bf2(fmaxf(acc[j][0] + bv0, 0.f), fmaxf(acc[j][1] + bv1, 0.f));
        u32 hi = f2bf2(fmaxf(acc[j][2] + bv0, 0.f), fmaxf(acc[j][3] + bv1, 0.f));
        Aw[(wrow + g) * ASTW + j * 4 + tc]     = lo;
        Aw[(wrow + g + 8) * ASTW + j * 4 + tc] = hi;
    }
    __syncthreads();
    for (int idx = tid; idx < 128 * 16; idx += 256) {
        int r = idx >> 4, q = idx & 15;
        if (row0 + r < NN)
            g_hbf[(size_t)(row0 + r) * 16 + q] = *(uint4*)(smc + SM_A + r * (AST * 2) + q * 16);
    }
}

// ---------------- K5: FUSED  Agg(h) + per-graph pool (16 rows / block) --------
__global__ void __launch_bounds__(256) agg_pool_kernel(const void* __restrict__ batch) {
    __shared__ float rows[16][128];
    __shared__ int rowg[16];
    int tid = threadIdx.x;
    int wid = tid >> 5, lane = tid & 31;
    int sub = lane & 15, half = lane >> 4;
    int r = wid * 2 + half;                // 0..15
    int dst = blockIdx.x * 16 + r;
    int is64 = g_is64;
    const uint4* sfh = (const uint4*)g_hbf;

    if (dst < NN) {
        float4 o0, o1;
        agg_row2_bf(sfh, dst, sub, o0, o1);
        *(float4*)(&rows[r][sub * 8])     = o0;
        *(float4*)(&rows[r][sub * 8 + 4]) = o1;
        if (sub == 0) rowg[r] = load_idx(batch, dst, is64) & (GG - 1);
    } else if (sub == 0) {
        rowg[r] = -1;
    }
    __syncthreads();

    if (tid < 128) {
        int t = tid;
        int cur = rowg[0];
        float acc = 0.f;
        #pragma unroll
        for (int rr = 0; rr < 16; rr++) {
            int g = rowg[rr];
            if (g < 0) break;
            if (g != cur) {
                atomicAdd(&g_sums[cur * HH + t], acc);
                acc = 0.f; cur = g;
            }
            acc += rows[rr][t];
        }
        if (cur >= 0) atomicAdd(&g_sums[cur * HH + t], acc);
    } else if (tid == 128) {
        int cur = rowg[0];
        float c = 0.f;
        #pragma unroll
        for (int rr = 0; rr < 16; rr++) {
            int g = rowg[rr];
            if (g < 0) break;
            if (g != cur) { atomicAdd(&g_cnt[cur], c); c = 0.f; cur = g; }
            c += 1.f;
        }
        if (cur >= 0) atomicAdd(&g_cnt[cur], c);
    }
}

// ---------------- K6: per-graph head: z = p@W2+b2 ; logits = z@Wlin+blin ------
__global__ void __launch_bounds__(128) final_kernel(const float* __restrict__ W2,
                                                    const float* __restrict__ b2,
                                                    const float* __restrict__ Wlin,
                                                    const float* __restrict__ blin,
                                                    float* __restrict__ out) {
    __shared__ float p[HH];
    __shared__ float z[HH];
    int g = blockIdx.x;            // 0..63
    int t = threadIdx.x;           // 0..127
    float inv = 1.f / fmaxf(g_cnt[g], 1.f);
    p[t] = g_sums[g * HH + t] * inv;
    __syncthreads();
    float s = b2[t];
    #pragma unroll 8
    for (int k = 0; k < HH; k++) s = fmaf(p[k], W2[k * HH + t], s);
    z[t] = s;
    __syncthreads();
    if (t < CC) {
        float l = blin[t];
        #pragma unroll 8
        for (int j = 0; j < HH; j++) l = fmaf(z[j], Wlin[j * CC + t], l);
        out[g * CC + t] = l;
    }
}

// ---------------- host launch ----------------
extern "C" void kernel_launch(void* const* d_in, const int* in_sizes, int n_in,
                              void* d_out, int out_size) {
    const float* x    = (const float*)d_in[0];
    const float* W1   = (const float*)d_in[1];
    const float* b1   = (const float*)d_in[2];
    const float* W2   = (const float*)d_in[3];
    const float* b2   = (const float*)d_in[4];
    const float* Wlin = (const float*)d_in[5];
    const float* blin = (const float*)d_in[6];
    const void*  ei   = d_in[7];   // edge_index: int32 or int64, detected on device
    const void*  bt   = d_in[8];   // batch: same index dtype
    float* out = (float*)d_out;

    cudaFuncSetAttribute(fused_agg_mma, cudaFuncAttributeMaxDynamicSharedMemorySize, FUSED_SMEM);

    zero_kernel<<<(NN + 255) / 256, 256>>>(ei);                 // + dtype detect
    prep_kernel<<<(NN * 16 + 255) / 256, 256>>>(x, ei);         // x->bf16 + degrees
    scan1_kernel<<<SCAN_NB, SCAN_T>>>();
    scan3_kernel<<<SCAN_NB, SCAN_T>>>();                        // inline block-sum reduce
    fill_kernel<<<(EE + 255) / 256, 256>>>(ei);

    // layer 1 fused: h = relu(Agg(x) @ W1 + b1)  (split-bf16 mma.sync)
    fused_agg_mma<<<(NN + 127) / 128, 256, FUSED_SMEM>>>(W1, b1);

    // layer 2 folded + fused: pool(Agg(h)); then per-graph head
    agg_pool_kernel<<<(NN + 15) / 16, 256>>>(bt);
    final_kernel<<<GG, 128>>>(W2, b2, Wlin, blin, out);
}

// round 15
// speedup vs baseline: 2.9741x; 1.0229x over previous
#include <cuda_runtime.h>
#include <cuda_bf16.h>
#include <cstdint>

// Problem constants (match reference)
#define NN 50000
#define EE 600000
#define GG 64
#define HH 128
#define CC 10

#define SCAN_T 256
#define SCAN_NB ((NN + SCAN_T - 1) / SCAN_T)   // 196

typedef unsigned long long u64;
typedef unsigned int u32;
typedef unsigned short u16;

// ---------------- scratch (static device globals; no runtime alloc) ----------------
// Zeroed-per-launch region: one contiguous memset.
struct ZReg {
    int   deg[NN];
    int   fill[NN];
    float sums[GG * HH];
    float cnt[GG];
};
__device__ ZReg g_z;
#define g_deg  g_z.deg
#define g_fill g_z.fill
#define g_sums g_z.sums
#define g_cnt  g_z.cnt

__device__ int   g_is64;           // 1 if index tensors are int64, 0 if int32
__device__ int   g_off[NN];        // CSR exclusive offsets
__device__ float g_dinv[NN];       // rsqrt(deg+1)
__device__ int   g_scan[NN];       // block-local inclusive scan of deg
__device__ int   g_bsum[SCAN_NB];  // per-block degree totals
__device__ int2  g_csr[EE];        // {src, bits(dinv[src])} grouped by dst
__device__ uint4 g_xbf[NN * 16];   // x in bf16 (row = 16 uint4 = 128 bf16)
__device__ uint4 g_hbf[NN * 16];   // h = relu(Agg(x)@W1+b1) in bf16
// Precomputed W1 split planes, pre-padded [n][136] bf16; hi plane then lo plane.
#define AST 136   // padded row stride in bf16
#define ASTW 68   // in 32-bit words
#define PLANE_U16 (128 * AST)              // 17408 u16 per plane
__device__ uint4 g_W1p[(PLANE_U16 * 2) / 8];   // 4352 uint4 = 69632 B

// ---------------- bf16 helpers ----------------
__device__ __forceinline__ float4 bf2f4(u32 a, u32 b) {
    __nv_bfloat162 p0 = *(__nv_bfloat162*)&a;
    __nv_bfloat162 p1 = *(__nv_bfloat162*)&b;
    float2 f0 = __bfloat1622float2(p0);
    float2 f1 = __bfloat1622float2(p1);
    return make_float4(f0.x, f0.y, f1.x, f1.y);
}
__device__ __forceinline__ u32 f2bf2(float a, float b) {
    __nv_bfloat162 p = __float22bfloat162_rn(make_float2(a, b));
    return *(u32*)&p;
}

// ---------------- warp-level bf16 MMA (sm_80+ PTX, legal on compute_103) -------
__device__ __forceinline__ void mma16816(float* d, u32 a0, u32 a1, u32 a2, u32 a3,
                                         u32 b0, u32 b1) {
    asm volatile(
        "mma.sync.aligned.m16n8k16.row.col.f32.bf16.bf16.f32 "
        "{%0,%1,%2,%3}, {%4,%5,%6,%7}, {%8,%9}, {%0,%1,%2,%3};"
        : "+f"(d[0]), "+f"(d[1]), "+f"(d[2]), "+f"(d[3])
        : "r"(a0), "r"(a1), "r"(a2), "r"(a3), "r"(b0), "r"(b1));
}

// ---------------- index load helper (dtype-agnostic) ----------------
__device__ __forceinline__ int load_idx(const void* p, long long i, int is64) {
    if (is64) return (int)(((const long long*)p)[i]);
    return ((const int*)p)[i];
}

// ---------------- K_detect: 1 block, decide int32 vs int64 ----------------
__global__ void detect_kernel(const void* ei) {
    __shared__ int bad;
    if (threadIdx.x == 0) bad = 0;
    __syncthreads();
    const long long* p = (const long long*)ei;
    for (int i = threadIdx.x; i < 1024; i += blockDim.x) {
        long long v = p[i];
        if (v < 0 || v >= (long long)NN) bad = 1;
    }
    __syncthreads();
    if (threadIdx.x == 0) g_is64 = bad ? 0 : 1;
}

// ---------------- K1: x->bf16, in-degrees, W1 split planes ----------------
__global__ void prep_kernel(const float* __restrict__ x, const void* __restrict__ ei,
                            const float* __restrict__ W1) {
    int i = blockIdx.x * blockDim.x + threadIdx.x;
    if (i < NN * 16) {
        float4 va = ((const float4*)x)[i * 2];
        float4 vb = ((const float4*)x)[i * 2 + 1];
        uint4 o;
        o.x = f2bf2(va.x, va.y);
        o.y = f2bf2(va.z, va.w);
        o.z = f2bf2(vb.x, vb.y);
        o.w = f2bf2(vb.z, vb.w);
        g_xbf[i] = o;
    }
    if (i < EE) {
        int is64 = g_is64;
        int dst = load_idx(ei, (long long)EE + i, is64);
        dst = min(max(dst, 0), NN - 1);
        atomicAdd(&g_deg[dst], 1);
    }
    if (i < 128 * 128) {
        int k = i >> 7, n = i & 127;
        float w = W1[i];
        __nv_bfloat16 hi = __float2bfloat16_rn(w);
        __nv_bfloat16 lo = __float2bfloat16_rn(w - __bfloat162float(hi));
        u16* planes = (u16*)g_W1p;
        planes[n * AST + k]             = *(u16*)&hi;
        planes[PLANE_U16 + n * AST + k] = *(u16*)&lo;
    }
}

// ---------------- K2a: per-block inclusive scan of deg (shfl-based) + dinv ----
__global__ void __launch_bounds__(SCAN_T) scan1_kernel() {
    __shared__ int ws[8];
    int b = blockIdx.x, t = threadIdx.x;
    int i = b * SCAN_T + t;
    int v = (i < NN) ? g_deg[i] : 0;
    if (i < NN) g_dinv[i] = rsqrtf((float)(v + 1));
    int lane = t & 31, w = t >> 5;
    int s = v;
    #pragma unroll
    for (int o = 1; o < 32; o <<= 1) {
        int u = __shfl_up_sync(0xffffffffu, s, o);
        if (lane >= o) s += u;
    }
    if (lane == 31) ws[w] = s;
    __syncthreads();
    if (w == 0 && lane < 8) {
        int x2 = ws[lane];
        #pragma unroll
        for (int o = 1; o < 8; o <<= 1) {
            int u = __shfl_up_sync(0xffu, x2, o, 8);
            if (lane >= o) x2 += u;
        }
        ws[lane] = x2;                      // inclusive warp sums
    }
    __syncthreads();
    if (w > 0) s += ws[w - 1];
    if (i < NN) g_scan[i] = s;              // inclusive within block
    if (t == SCAN_T - 1) g_bsum[b] = s;
}

// ---------------- K2b: block base (shfl reduce of preceding sums) + offsets ---
__global__ void __launch_bounds__(SCAN_T) scan3_kernel() {
    __shared__ int ws[8];
    __shared__ int sbase;
    int b = blockIdx.x, t = threadIdx.x;
    int lane = t & 31, w = t >> 5;
    int val = (t < b && t < SCAN_NB) ? g_bsum[t] : 0;
    #pragma unroll
    for (int o = 16; o > 0; o >>= 1) val += __shfl_down_sync(0xffffffffu, val, o);
    if (lane == 0) ws[w] = val;
    __syncthreads();
    if (t == 0) {
        int s = 0;
        #pragma unroll
        for (int j = 0; j < 8; j++) s += ws[j];
        sbase = s;
    }
    __syncthreads();
    int i = b * SCAN_T + t;
    if (i < NN) g_off[i] = sbase + g_scan[i] - g_deg[i];
}

// ---------------- K3: scatter edges into dst-grouped CSR ----------------
__global__ void fill_kernel(const void* __restrict__ ei) {
    int e = blockIdx.x * blockDim.x + threadIdx.x;
    if (e < EE) {
        int is64 = g_is64;
        int src = load_idx(ei, e, is64);
        int dst = load_idx(ei, (long long)EE + e, is64);
        src = min(max(src, 0), NN - 1);
        dst = min(max(dst, 0), NN - 1);
        int pos = g_off[dst] + atomicAdd(&g_fill[dst], 1);
        g_csr[pos] = make_int2(src, __float_as_int(g_dinv[src]));
    }
}

// ---------------- dual-row agg (predicated batch-4, no serial tail) -----------
__device__ __forceinline__ void fma4(float4& a, float w, const float4& v) {
    a.x = fmaf(w, v.x, a.x); a.y = fmaf(w, v.y, a.y);
    a.z = fmaf(w, v.z, a.z); a.w = fmaf(w, v.w, a.w);
}

__device__ __forceinline__ void agg_row2_bf(const uint4* __restrict__ sf, int dst, int sub,
                                            float4& o0, float4& o1) {
    float di = g_dinv[dst];
    uint4 sv = sf[dst * 16 + sub];                 // self loop
    float4 a0 = bf2f4(sv.x, sv.y);
    float4 a1 = bf2f4(sv.z, sv.w);
    a0.x *= di; a0.y *= di; a0.z *= di; a0.w *= di;
    a1.x *= di; a1.y *= di; a1.z *= di; a1.w *= di;
    float4 b0 = make_float4(0.f, 0.f, 0.f, 0.f);
    float4 b1 = make_float4(0.f, 0.f, 0.f, 0.f);

    int e0 = g_off[dst];
    int end = e0 + g_deg[dst];
    int last = end - 1;
    for (int b = e0; b < end; b += 4) {
        int i1 = b + 1, i2 = b + 2, i3 = b + 3;
        int2 c0 = g_csr[b];
        int2 c1 = g_csr[min(i1, last)];
        int2 c2 = g_csr[min(i2, last)];
        int2 c3 = g_csr[min(i3, last)];
        uint4 v0 = sf[c0.x * 16 + sub];
        uint4 v1 = sf[c1.x * 16 + sub];
        uint4 v2 = sf[c2.x * 16 + sub];
        uint4 v3 = sf[c3.x * 16 + sub];
        float w0 = __int_as_float(c0.y);
        float w1 = (i1 < end) ? __int_as_float(c1.y) : 0.f;
        float w2 = (i2 < end) ? __int_as_float(c2.y) : 0.f;
        float w3 = (i3 < end) ? __int_as_float(c3.y) : 0.f;
        fma4(a0, w0, bf2f4(v0.x, v0.y)); fma4(a1, w0, bf2f4(v0.z, v0.w));
        fma4(b0, w1, bf2f4(v1.x, v1.y)); fma4(b1, w1, bf2f4(v1.z, v1.w));
        fma4(a0, w2, bf2f4(v2.x, v2.y)); fma4(a1, w2, bf2f4(v2.z, v2.w));
        fma4(b0, w3, bf2f4(v3.x, v3.y)); fma4(b1, w3, bf2f4(v3.z, v3.w));
    }
    a0.x += b0.x; a0.y += b0.y; a0.z += b0.z; a0.w += b0.w;
    a1.x += b1.x; a1.y += b1.y; a1.z += b1.z; a1.w += b1.w;
    a0.x *= di; a0.y *= di; a0.z *= di; a0.w *= di;
    a1.x *= di; a1.y *= di; a1.z *= di; a1.w *= di;
    o0 = a0; o1 = a1;
}

// ---------------- K4: FUSED  h = relu(Agg(x) @ W1 + b1) via split-bf16 MMA ----
// SMEM: [512:1024) bias fp32, [1024,+34816) A bf16 [128][136],
//       [35840,+69632) Bhi+Blo planes (copied as uint4 from g_W1p).
#define SM_BIAS 512
#define SM_A 1024
#define SM_BHI (1024 + 34816)
#define SM_BLO (1024 + 34816 + 34816)
#define FUSED_SMEM (1024 + 34816 + 34816 + 34816)

__global__ void __launch_bounds__(256, 2)
fused_agg_mma(const float* __restrict__ b1) {
    extern __shared__ char smc[];
    float* bias_s = (float*)(smc + SM_BIAS);
    u32* Aw  = (u32*)(smc + SM_A);
    u32* BwH = (u32*)(smc + SM_BHI);
    u32* BwL = (u32*)(smc + SM_BLO);
    int tid = threadIdx.x;
    int wid = tid >> 5, lane = tid & 31;
    int sub = lane & 15, half = lane >> 4;
    int row0 = blockIdx.x * 128;

    if (tid < 128) bias_s[tid] = b1[tid];

    // ---- B planes: straight uint4 copy of precomputed Whi/Wlo ----
    uint4* bdst = (uint4*)(smc + SM_BHI);
    #pragma unroll 4
    for (int i = tid; i < (PLANE_U16 * 2) / 8; i += 256)
        bdst[i] = g_W1p[i];

    // ---- A tile: aggregate 128 rows into As[m][k] bf16 (stride 136) ----
    const uint4* sfx = (const uint4*)g_xbf;
    #pragma unroll 1
    for (int r = 0; r < 8; r++) {
        int m = wid * 16 + r * 2 + half;
        int dst = row0 + m;
        float4 o0 = make_float4(0.f, 0.f, 0.f, 0.f);
        float4 o1 = make_float4(0.f, 0.f, 0.f, 0.f);
        if (dst < NN) agg_row2_bf(sfx, dst, sub, o0, o1);
        uint4 pk;
        pk.x = f2bf2(o0.x, o0.y); pk.y = f2bf2(o0.z, o0.w);
        pk.z = f2bf2(o1.x, o1.y); pk.w = f2bf2(o1.z, o1.w);
        *(uint4*)(smc + SM_A + m * (AST * 2) + sub * 16) = pk;
    }
    __syncthreads();

    // ---- MMA: each warp computes rows [wid*16, +16) x all 128 cols ----
    int g = lane >> 2, tc = lane & 3;
    int wrow = wid * 16;
    float acc[16][4];
    #pragma unroll
    for (int j = 0; j < 16; j++)
        #pragma unroll
        for (int q = 0; q < 4; q++) acc[j][q] = 0.f;

    #pragma unroll 1
    for (int ks = 0; ks < 8; ks++) {
        int k0w = ks * 8;                       // 16 bf16 = 8 words
        u32 a0 = Aw[(wrow + g) * ASTW + k0w + tc];
        u32 a1 = Aw[(wrow + g + 8) * ASTW + k0w + tc];
        u32 a2 = Aw[(wrow + g) * ASTW + k0w + tc + 4];
        u32 a3 = Aw[(wrow + g + 8) * ASTW + k0w + tc + 4];
        #pragma unroll
        for (int j = 0; j < 16; j++) {
            int bi = (j * 8 + g) * ASTW + k0w + tc;
            u32 bh0 = BwH[bi], bh1 = BwH[bi + 4];
            u32 bl0 = BwL[bi], bl1 = BwL[bi + 4];
            mma16816(acc[j], a0, a1, a2, a3, bh0, bh1);
            mma16816(acc[j], a0, a1, a2, a3, bl0, bl1);
        }
    }
    __syncthreads();     // done reading As/Bs; reuse As for output staging

    // ---- epilogue: bias + relu, pack bf16 into As, then coalesced store ----
    #pragma unroll
    for (int j = 0; j < 16; j++) {
        int c = j * 8 + tc * 2;
        float bv0 = bias_s[c], bv1 = bias_s[c + 1];
        u32 lo = f2bf2(fmaxf(acc[j][0] + bv0, 0.f), fmaxf(acc[j][1] + bv1, 0.f));
        u32 hi = f2bf2(fmaxf(acc[j][2] + bv0, 0.f), fmaxf(acc[j][3] + bv1, 0.f));
        Aw[(wrow + g) * ASTW + j * 4 + tc]     = lo;
        Aw[(wrow + g + 8) * ASTW + j * 4 + tc] = hi;
    }
    __syncthreads();
    for (int idx = tid; idx < 128 * 16; idx += 256) {
        int r = idx >> 4, q = idx & 15;
        if (row0 + r < NN)
            g_hbf[(size_t)(row0 + r) * 16 + q] = *(uint4*)(smc + SM_A + r * (AST * 2) + q * 16);
    }
}

// ---------------- K5: FUSED  Agg(h) + per-graph pool (16 rows / block) --------
__global__ void __launch_bounds__(256) agg_pool_kernel(const void* __restrict__ batch) {
    __shared__ float rows[16][128];
    __shared__ int rowg[16];
    int tid = threadIdx.x;
    int wid = tid >> 5, lane = tid & 31;
    int sub = lane & 15, half = lane >> 4;
    int r = wid * 2 + half;                // 0..15
    int dst = blockIdx.x * 16 + r;
    int is64 = g_is64;
    const uint4* sfh = (const uint4*)g_hbf;

    if (dst < NN) {
        float4 o0, o1;
        agg_row2_bf(sfh, dst, sub, o0, o1);
        *(float4*)(&rows[r][sub * 8])     = o0;
        *(float4*)(&rows[r][sub * 8 + 4]) = o1;
        if (sub == 0) rowg[r] = load_idx(batch, dst, is64) & (GG - 1);
    } else if (sub == 0) {
        rowg[r] = -1;
    }
    __syncthreads();

    if (tid < 128) {
        int t = tid;
        int cur = rowg[0];
        float acc = 0.f;
        #pragma unroll
        for (int rr = 0; rr < 16; rr++) {
            int g = rowg[rr];
            if (g < 0) break;
            if (g != cur) {
                atomicAdd(&g_sums[cur * HH + t], acc);
                acc = 0.f; cur = g;
            }
            acc += rows[rr][t];
        }
        if (cur >= 0) atomicAdd(&g_sums[cur * HH + t], acc);
    } else if (tid == 128) {
        int cur = rowg[0];
        float c = 0.f;
        #pragma unroll
        for (int rr = 0; rr < 16; rr++) {
            int g = rowg[rr];
            if (g < 0) break;
            if (g != cur) { atomicAdd(&g_cnt[cur], c); c = 0.f; cur = g; }
            c += 1.f;
        }
        if (cur >= 0) atomicAdd(&g_cnt[cur], c);
    }
}

// ---------------- K6: per-graph head: z = p@W2+b2 ; logits = z@Wlin+blin ------
__global__ void __launch_bounds__(128) final_kernel(const float* __restrict__ W2,
                                                    const float* __restrict__ b2,
                                                    const float* __restrict__ Wlin,
                                                    const float* __restrict__ blin,
                                                    float* __restrict__ out) {
    __shared__ float p[HH];
    __shared__ float z[HH];
    int g = blockIdx.x;            // 0..63
    int t = threadIdx.x;           // 0..127
    float inv = 1.f / fmaxf(g_cnt[g], 1.f);
    p[t] = g_sums[g * HH + t] * inv;
    __syncthreads();
    float s = b2[t];
    #pragma unroll 8
    for (int k = 0; k < HH; k++) s = fmaf(p[k], W2[k * HH + t], s);
    z[t] = s;
    __syncthreads();
    if (t < CC) {
        float l = blin[t];
        #pragma unroll 8
        for (int j = 0; j < HH; j++) l = fmaf(z[j], Wlin[j * CC + t], l);
        out[g * CC + t] = l;
    }
}

// ---------------- host launch ----------------
extern "C" void kernel_launch(void* const* d_in, const int* in_sizes, int n_in,
                              void* d_out, int out_size) {
    const float* x    = (const float*)d_in[0];
    const float* W1   = (const float*)d_in[1];
    const float* b1   = (const float*)d_in[2];
    const float* W2   = (const float*)d_in[3];
    const float* b2   = (const float*)d_in[4];
    const float* Wlin = (const float*)d_in[5];
    const float* blin = (const float*)d_in[6];
    const void*  ei   = d_in[7];   // edge_index: int32 or int64, detected on device
    const void*  bt   = d_in[8];   // batch: same index dtype
    float* out = (float*)d_out;

    cudaFuncSetAttribute(fused_agg_mma, cudaFuncAttributeMaxDynamicSharedMemorySize, FUSED_SMEM);

    void* zp;
    cudaGetSymbolAddress(&zp, g_z);
    cudaMemsetAsync(zp, 0, sizeof(ZReg));                       // zero deg/fill/sums/cnt

    detect_kernel<<<1, 256>>>(ei);
    prep_kernel<<<(NN * 16 + 255) / 256, 256>>>(x, ei, W1);     // x->bf16 + deg + W1 split
    scan1_kernel<<<SCAN_NB, SCAN_T>>>();
    scan3_kernel<<<SCAN_NB, SCAN_T>>>();
    fill_kernel<<<(EE + 255) / 256, 256>>>(ei);

    // layer 1 fused: h = relu(Agg(x) @ W1 + b1)  (split-bf16 mma.sync)
    fused_agg_mma<<<(NN + 127) / 128, 256, FUSED_SMEM>>>(b1);

    // layer 2 folded + fused: pool(Agg(h)); then per-graph head
    agg_pool_kernel<<<(NN + 15) / 16, 256>>>(bt);
    final_kernel<<<GG, 128>>>(W2, b2, Wlin, blin, out);
}